// round 12
// baseline (speedup 1.0000x reference)
#include <cuda_runtime.h>
#include <cuda_bf16.h>
#include <cstdint>
#include <math.h>

#define Bq  16
#define Tq  1024
#define Dq  256
#define Cq  1024
#define Kq  9
#define BH  (Bq / 2)   // batches per phase

// ===========================================================================
// Helpers (baseline PTX only — no 'a'-suffix features)
// ===========================================================================
__device__ __forceinline__ uint32_t smem_to_u32(const void* p) {
    uint32_t a;
    asm("{ .reg .u64 t; cvta.to.shared.u64 t, %1; cvt.u32.u64 %0, t; }" : "=r"(a) : "l"(p));
    return a;
}
#define LDSM_X4(r, a) \
    asm volatile("ldmatrix.sync.aligned.m8n8.x4.shared.b16 {%0,%1,%2,%3}, [%4];" \
        : "=r"((r)[0]), "=r"((r)[1]), "=r"((r)[2]), "=r"((r)[3]) : "r"(a))
#define MMA_BF16(d, a, bb) \
    asm volatile("mma.sync.aligned.m16n8k16.row.col.f32.bf16.bf16.f32 " \
        "{%0,%1,%2,%3}, {%4,%5,%6,%7}, {%8,%9}, {%0,%1,%2,%3};" \
        : "+f"((d)[0]), "+f"((d)[1]), "+f"((d)[2]), "+f"((d)[3]) \
        : "r"((a)[0]), "r"((a)[1]), "r"((a)[2]), "r"((a)[3]), \
          "r"((bb)[0]), "r"((bb)[1]))

#define MBARRIER_INIT(mb, c) \
    asm volatile("mbarrier.init.shared.b64 [%0], %1;" :: "r"((uint32_t)(mb)), "r"((uint32_t)(c)) : "memory")
#define MBARRIER_WAIT_PARITY(mb, ph) do { \
    uint32_t _m = (uint32_t)(mb); uint32_t _p = (uint32_t)(ph); uint32_t _d; \
    asm volatile("{\n\t.reg .pred p;\n\t" \
        "mbarrier.try_wait.parity.acquire.cta.shared::cta.b64 p, [%1], %2;\n\t" \
        "selp.b32 %0, 1, 0, p;\n\t}" : "=r"(_d) : "r"(_m), "r"(_p) : "memory"); \
    if (!_d) { \
        asm volatile("{\n\t.reg .pred P1;\n\t" \
            "WL_%=:\n\t" \
            "mbarrier.try_wait.parity.acquire.cta.shared::cta.b64 P1, [%0], %1, 0x989680;\n\t" \
            "@P1 bra.uni WD_%=;\n\t" \
            "bra.uni WL_%=;\n\t" \
            "WD_%=:\n\t}" :: "r"(_m), "r"(_p) : "memory"); \
    } } while (0)

__device__ __forceinline__ void bulk_ld(uint32_t dst, const void* src, uint32_t mb) {
    asm volatile(
        "cp.async.bulk.shared::cta.global.mbarrier::complete_tx::bytes [%0], [%1], %2, [%3];"
        :: "r"(dst), "l"(src), "r"(8192u), "r"(mb) : "memory");
}
__device__ __forceinline__ void mbar_expect(uint32_t mb, uint32_t bytes) {
    asm volatile("mbarrier.arrive.expect_tx.shared.b64 _, [%0], %1;"
        :: "r"(mb), "r"(bytes) : "memory");
}

// mish(x) = x * w / (w + 2),  w = e^x (e^x + 2)
__device__ __forceinline__ float mishf(float x) {
    if (x > 15.f) return x;
    float t = __expf(x);
    float w = t * (t + 2.f);
    return x * __fdividef(w, w + 2.f);
}
__device__ __forceinline__ void bsplit(float v, __nv_bfloat16& h, __nv_bfloat16& l) {
    h = __float2bfloat16(v);
    l = __float2bfloat16(v - __bfloat162float(h));
}
__device__ __forceinline__ uint32_t pkbf(__nv_bfloat16 a, __nv_bfloat16 b) {
    __nv_bfloat162 t{a, b};
    return *(uint32_t*)&t;
}

// Packed layout: matrix [R rows][K cols] bf16 -> blocks of 128 rows x 32 k
// (8192 B, chunk-contiguous). Within block: phys row p = r>>1 (128 B),
// 16B segment index = (((r&1)<<2)|s) ^ (p&7), s = (k%32)>>3.
__device__ __forceinline__ size_t pk_off(int m, int q, int r, int s, int nq) {
    int p = r >> 1;
    int seg = ((((r & 1) << 2) | s) ^ (p & 7));
    return ((size_t)(m * nq + q) << 13) + ((size_t)p << 7) + ((size_t)seg << 4);
}

// ===========================================================================
// Device scratch
// ===========================================================================
__device__ __align__(16) __nv_bfloat16 g_xhi[(size_t)Bq * Tq * Dq];     // packed
__device__ __align__(16) __nv_bfloat16 g_xlo[(size_t)Bq * Tq * Dq];
__device__ __align__(16) __nv_bfloat16 g_w1hi[(size_t)Cq * Dq];         // packed
__device__ __align__(16) __nv_bfloat16 g_w1lo[(size_t)Cq * Dq];
__device__ __align__(16) __nv_bfloat16 g_w2hi[(size_t)Dq * Cq];         // packed
__device__ __align__(16) __nv_bfloat16 g_w2lo[(size_t)Dq * Cq];
__device__ __align__(16) float g_hT[(size_t)Bq * Tq * Cq];              // plain [b][t][c]
__device__ __align__(16) __nv_bfloat16 g_convhi[(size_t)Bq * Tq * Cq];  // packed
__device__ __align__(16) __nv_bfloat16 g_convlo[(size_t)Bq * Tq * Cq];
__device__ __align__(16) __nv_bfloat16 g_pwhi[(size_t)Bq * Cq * Cq];    // packed
__device__ __align__(16) __nv_bfloat16 g_pwlo[(size_t)Bq * Cq * Cq];
__device__ __align__(16) __nv_bfloat16 g_tmphi[(size_t)Bq * Tq * Cq];   // packed
__device__ __align__(16) __nv_bfloat16 g_tmplo[(size_t)Bq * Tq * Cq];
__device__ float g_inv_pnorm[Bq * Cq];
__device__ float g_inv_dnorm[Bq * Kq];

// ===========================================================================
// Prep kernels
// ===========================================================================
__global__ void split_pack_kernel(const float* __restrict__ src,
                                  __nv_bfloat16* __restrict__ hi,
                                  __nv_bfloat16* __restrict__ lo,
                                  int lgspr, int nq, int total) {
    int idx = blockIdx.x * 256 + threadIdx.x;
    if (idx >= total) return;
    int spr = 1 << lgspr;
    int r_all = idx >> lgspr;
    int kseg = idx & (spr - 1);
    int q = kseg >> 2, s = kseg & 3;
    int m = r_all >> 7, r = r_all & 127;
    const float* sp = src + ((size_t)r_all << (lgspr + 3)) + ((size_t)kseg << 3);
    float4 v0 = *(const float4*)sp;
    float4 v1 = *(const float4*)(sp + 4);
    __nv_bfloat16 h[8], l[8];
    bsplit(v0.x, h[0], l[0]); bsplit(v0.y, h[1], l[1]);
    bsplit(v0.z, h[2], l[2]); bsplit(v0.w, h[3], l[3]);
    bsplit(v1.x, h[4], l[4]); bsplit(v1.y, h[5], l[5]);
    bsplit(v1.z, h[6], l[6]); bsplit(v1.w, h[7], l[7]);
    size_t off = pk_off(m, q, r, s, nq);
    uint4 hv = make_uint4(pkbf(h[0],h[1]), pkbf(h[2],h[3]), pkbf(h[4],h[5]), pkbf(h[6],h[7]));
    uint4 lv = make_uint4(pkbf(l[0],l[1]), pkbf(l[2],l[3]), pkbf(l[4],l[5]), pkbf(l[6],l[7]));
    *(uint4*)((char*)hi + off) = hv;
    *(uint4*)((char*)lo + off) = lv;
}

__global__ void dnorm_kernel(const float* __restrict__ d_w) {
    int bk = blockIdx.x;
    int b = bk / Kq, k = bk % Kq;
    float s = 0.f;
    for (int c = threadIdx.x; c < Cq; c += 256) {
        float v = d_w[((size_t)b * Cq + c) * Kq + k];
        s = fmaf(v, v, s);
    }
    __shared__ float red[256];
    red[threadIdx.x] = s;
    __syncthreads();
    for (int off = 128; off > 0; off >>= 1) {
        if (threadIdx.x < off) red[threadIdx.x] += red[threadIdx.x + off];
        __syncthreads();
    }
    if (threadIdx.x == 0)
        g_inv_dnorm[bk] = 1.f / fmaxf(sqrtf(red[0]), 1e-12f);
}

__global__ void pnorm_kernel(const float* __restrict__ p_w) {
    int b = blockIdx.x;
    int o = blockIdx.y * 256 + threadIdx.x;
    const float* base = p_w + (size_t)b * Cq * Cq + o;
    float s = 0.f;
    #pragma unroll 4
    for (int c = 0; c < Cq; ++c) {
        float v = base[(size_t)c * Cq];
        s = fmaf(v, v, s);
    }
    g_inv_pnorm[b * Cq + o] = 1.f / fmaxf(sqrtf(s), 1e-12f);
}

// Transpose p_w[b][c][o]*p_g[b][c] -> packed [b*1024+o rows][c cols] bf16 split
__global__ __launch_bounds__(256) void pw_prep_kernel(
    const float* __restrict__ p_w, const float* __restrict__ p_g) {
    int b = blockIdx.z;
    int c0 = blockIdx.x * 32;
    int o0 = blockIdx.y * 32;
    __shared__ float s[32][33];
    __shared__ float pgs[32];
    int tid = threadIdx.x;
    int x = tid & 31, y = tid >> 5;
    if (tid < 32) pgs[tid] = p_g[b * Cq + c0 + tid];
    const float* in = p_w + (size_t)b * Cq * Cq;
    #pragma unroll
    for (int yy = 0; yy < 4; ++yy) {
        int c = c0 + y * 4 + yy;
        s[y * 4 + yy][x] = in[(size_t)c * Cq + o0 + x];
    }
    __syncthreads();
    int q = c0 >> 5;
    int sseg = x >> 3;
    int ins = (x & 7) << 1;
    #pragma unroll
    for (int yy = 0; yy < 4; ++yy) {
        int o = o0 + y * 4 + yy;
        float w = s[x][y * 4 + yy] * pgs[x];
        __nv_bfloat16 h, l;
        bsplit(w, h, l);
        int m = (b << 3) | (o >> 7);
        size_t off = pk_off(m, q, o & 127, sseg, 32) + ins;
        *(__nv_bfloat16*)((char*)g_pwhi + off) = h;
        *(__nv_bfloat16*)((char*)g_pwlo + off) = l;
    }
}

// ===========================================================================
// Depthwise conv on [t][c] layout -> packed bf16 split (batch-offset b0)
// ===========================================================================
__global__ __launch_bounds__(256) void conv_t_kernel(
    const float* __restrict__ d_w, const float* __restrict__ d_g,
    const float* __restrict__ d_b, int b0) {
    int b  = blockIdx.z + b0;
    int t0 = blockIdx.y * 8;
    int ch = blockIdx.x * 512;
    __shared__ float s[16][512];
    const float* h = g_hT + (size_t)b * Tq * Cq;
    int tid = threadIdx.x;
    #pragma unroll
    for (int i = 0; i < 8; ++i) {
        int idx = tid + i * 256;
        int r  = idx >> 7;
        int cc = (idx & 127) * 4;
        int t = t0 - 4 + r;
        float4 v = (t >= 0 && t < Tq)
            ? *(const float4*)(h + (size_t)t * Cq + ch + cc)
            : make_float4(0.f, 0.f, 0.f, 0.f);
        *(float4*)&s[r][cc] = v;
    }
    __syncthreads();
    int cg = (tid & 127) * 4;
    int tsub = tid >> 7;
    int c = ch + cg;
    float w[Kq][4], bias[4];
    #pragma unroll
    for (int qd = 0; qd < 4; ++qd) {
        float g = d_g[b * Cq + c + qd];
        bias[qd] = d_b[b * Cq + c + qd];
        #pragma unroll
        for (int k = 0; k < Kq; ++k)
            w[k][qd] = d_w[((size_t)b * Cq + c + qd) * Kq + k] * g_inv_dnorm[b * Kq + k] * g;
    }
    int qc = c >> 5;
    int sc = (c >> 3) & 3;
    int ins = (c & 7) << 1;
    #pragma unroll
    for (int i = 0; i < 4; ++i) {
        int tl = tsub * 4 + i;
        int t = t0 + tl;
        float4 acc = make_float4(bias[0], bias[1], bias[2], bias[3]);
        #pragma unroll
        for (int k = 0; k < Kq; ++k) {
            float4 vv = *(float4*)&s[tl + k][cg];
            acc.x = fmaf(vv.x, w[k][0], acc.x);
            acc.y = fmaf(vv.y, w[k][1], acc.y);
            acc.z = fmaf(vv.z, w[k][2], acc.z);
            acc.w = fmaf(vv.w, w[k][3], acc.w);
        }
        __nv_bfloat16 h0, h1, h2, h3, l0, l1, l2, l3;
        bsplit(acc.x, h0, l0); bsplit(acc.y, h1, l1);
        bsplit(acc.z, h2, l2); bsplit(acc.w, h3, l3);
        int m = (b << 3) | (t >> 7);
        size_t off = pk_off(m, qc, t & 127, sc, 32) + ins;
        *(uint2*)((char*)g_convhi + off) = make_uint2(pkbf(h0,h1), pkbf(h2,h3));
        *(uint2*)((char*)g_convlo + off) = make_uint2(pkbf(l0,l1), pkbf(l2,l3));
    }
}

// ===========================================================================
// mma.sync bf16-split GEMM with cp.async.bulk chunk loads.
// CTA tile 128x128, K-chunk 32, 2 stages x 32KB, 2 CTAs/SM.
// R8 sync structure + intra-ks load/MMA interleave. Batch-offset b0.
// ===========================================================================
#define STAGE_B 32768
#define SMEM_ALLOC (1024 + 128 + 2 * STAGE_B)

__device__ __forceinline__ void issue_chunk(uint32_t st0, uint32_t mbf,
    const char* Ah, const char* Al, const char* Bh, const char* Bl, int q) {
    int buf = q & 1;
    uint32_t mb = mbf + (uint32_t)buf * 8u;
    uint32_t dst = st0 + (uint32_t)buf * STAGE_B;
    size_t qo = (size_t)q << 13;
    mbar_expect(mb, 32768u);
    bulk_ld(dst,          Ah + qo, mb);
    bulk_ld(dst + 8192u,  Al + qo, mb);
    bulk_ld(dst + 16384u, Bh + qo, mb);
    bulk_ld(dst + 24576u, Bl + qo, mb);
}

template <int EPI>
__global__ __launch_bounds__(256, 2) void mma_gemm(
    const __nv_bfloat16* __restrict__ Ahi, const __nv_bfloat16* __restrict__ Alo,
    int a_mpb,
    const __nv_bfloat16* __restrict__ Bhi, const __nv_bfloat16* __restrict__ Blo,
    int b_mpb,
    int nchunks, int b0,
    const float* __restrict__ e0, const float* __restrict__ e1,
    float* __restrict__ out0) {
    extern __shared__ __align__(128) char dsm[];
    uint32_t raw = smem_to_u32(dsm);
    uint32_t hdr = (raw + 1023u) & ~1023u;
    uint32_t mbf = hdr;
    uint32_t st0 = hdr + 128;
    int tid = threadIdx.x;
    int wid = tid >> 5, lane = tid & 31;
    int wm = wid >> 2, wn = wid & 3;
    int b = blockIdx.z + b0, m0 = blockIdx.y * 128, n0 = blockIdx.x * 128;

    const char* Abh = (const char*)Ahi + ((size_t)((b * a_mpb + blockIdx.y) * nchunks) << 13);
    const char* Abl = (const char*)Alo + ((size_t)((b * a_mpb + blockIdx.y) * nchunks) << 13);
    const char* Bbh = (const char*)Bhi + ((size_t)((b * b_mpb + blockIdx.x) * nchunks) << 13);
    const char* Bbl = (const char*)Blo + ((size_t)((b * b_mpb + blockIdx.x) * nchunks) << 13);

    if (tid == 0) {
        MBARRIER_INIT(mbf, 1);
        MBARRIER_INIT(mbf + 8, 1);
    }
    __syncthreads();
    if (tid == 0) {
        issue_chunk(st0, mbf, Abh, Abl, Bbh, Bbl, 0);
        issue_chunk(st0, mbf, Abh, Abl, Bbh, Bbl, 1);
    }

    uint32_t aoff[4][2], boff4[2][2];
    {
        int rla = lane & 15, sha = (lane >> 4) & 1;
        #pragma unroll
        for (int i = 0; i < 4; ++i) {
            int r = wm * 64 + i * 16 + rla;
            int p = r >> 1, x4 = (r & 1) << 2, mk = p & 7, rb = p << 7;
            aoff[i][0] = rb + (((x4 | sha) ^ mk) << 4);
            aoff[i][1] = rb + (((x4 | (2 + sha)) ^ mk) << 4);
        }
        int rlb = lane & 7;
        int shb = (lane >> 3) & 1;
        int jsel = (lane >> 4) & 1;
        #pragma unroll
        for (int J = 0; J < 2; ++J) {
            int r = wn * 32 + (J * 2 + jsel) * 8 + rlb;
            int p = r >> 1, x4 = (r & 1) << 2, mk = p & 7, rb = p << 7;
            boff4[J][0] = rb + (((x4 | shb) ^ mk) << 4);
            boff4[J][1] = rb + (((x4 | (2 + shb)) ^ mk) << 4);
        }
    }

    float acc[4][4][4] = {};

    for (int q = 0; q < nchunks; ++q) {
        int buf = q & 1;
        MBARRIER_WAIT_PARITY(mbf + (uint32_t)buf * 8u, (q >> 1) & 1);
        uint32_t st = st0 + (uint32_t)buf * STAGE_B;
        #pragma unroll
        for (int ks = 0; ks < 2; ++ks) {
            uint32_t ah[4][4], al[4][4], bh[4][2], bl[4][2];
            #pragma unroll
            for (int J = 0; J < 2; ++J) {
                LDSM_X4(&bh[J * 2][0], st + 16384u + boff4[J][ks]);
                LDSM_X4(&bl[J * 2][0], st + 24576u + boff4[J][ks]);
            }
            #pragma unroll
            for (int i = 0; i < 4; ++i)
                LDSM_X4(ah[i], st + aoff[i][ks]);
            #pragma unroll
            for (int i = 0; i < 4; ++i)
                #pragma unroll
                for (int jj = 0; jj < 4; ++jj)
                    MMA_BF16(acc[i][jj], ah[i], bh[jj]);
            #pragma unroll
            for (int i = 0; i < 4; ++i)
                LDSM_X4(al[i], st + 8192u + aoff[i][ks]);
            #pragma unroll
            for (int i = 0; i < 4; ++i)
                #pragma unroll
                for (int jj = 0; jj < 4; ++jj)
                    MMA_BF16(acc[i][jj], ah[i], bl[jj]);
            #pragma unroll
            for (int i = 0; i < 4; ++i)
                #pragma unroll
                for (int jj = 0; jj < 4; ++jj)
                    MMA_BF16(acc[i][jj], al[i], bh[jj]);
        }
        __syncthreads();
        if (q + 2 < nchunks && tid == 0)
            issue_chunk(st0, mbf, Abh, Abl, Bbh, Bbl, q + 2);
    }

    int gid = lane >> 2, tig = lane & 3;
    #pragma unroll
    for (int i = 0; i < 4; ++i) {
        int r0 = m0 + wm * 64 + i * 16 + gid;
        #pragma unroll
        for (int jj = 0; jj < 4; ++jj) {
            int col = n0 + wn * 32 + jj * 8 + tig * 2;
            float v0 = acc[i][jj][0], v1 = acc[i][jj][1];
            float v2 = acc[i][jj][2], v3 = acc[i][jj][3];
            if (EPI == 1) {
                float b0v = e0[col], b1v = e0[col + 1];
                float* d0 = g_hT + ((size_t)b * Tq + r0) * Cq + col;
                float* d1 = g_hT + ((size_t)b * Tq + r0 + 8) * Cq + col;
                *(float2*)d0 = float2{mishf(v0 + b0v), mishf(v1 + b1v)};
                *(float2*)d1 = float2{mishf(v2 + b0v), mishf(v3 + b1v)};
            } else if (EPI == 2) {
                float s0 = g_inv_pnorm[b * Cq + col], s1 = g_inv_pnorm[b * Cq + col + 1];
                float p0 = e0[b * Cq + col], p1 = e0[b * Cq + col + 1];
                float u0 = mishf(fmaf(v0, s0, p0)), u1 = mishf(fmaf(v1, s1, p1));
                float u2 = mishf(fmaf(v2, s0, p0)), u3 = mishf(fmaf(v3, s1, p1));
                __nv_bfloat16 h0, h1, h2, h3, l0, l1, l2, l3;
                bsplit(u0, h0, l0); bsplit(u1, h1, l1);
                bsplit(u2, h2, l2); bsplit(u3, h3, l3);
                int m = (b << 3) | (r0 >> 7);
                int qp = col >> 5, sp = (col >> 3) & 3, ins = (col & 7) << 1;
                size_t oA = pk_off(m, qp, r0 & 127, sp, 32) + ins;
                size_t oB = pk_off(m, qp, (r0 + 8) & 127, sp, 32) + ins;
                *(uint32_t*)((char*)g_tmphi + oA) = pkbf(h0, h1);
                *(uint32_t*)((char*)g_tmphi + oB) = pkbf(h2, h3);
                *(uint32_t*)((char*)g_tmplo + oA) = pkbf(l0, l1);
                *(uint32_t*)((char*)g_tmplo + oB) = pkbf(l2, l3);
            } else {
                float b0v = e0[col], b1v = e0[col + 1];
                size_t o0i = ((size_t)b * Tq + r0) * Dq + col;
                size_t o1i = ((size_t)b * Tq + r0 + 8) * Dq + col;
                float2 x0 = *(const float2*)(e1 + o0i);
                float2 x1 = *(const float2*)(e1 + o1i);
                *(float2*)(out0 + o0i) = float2{v0 + b0v + x0.x, v1 + b1v + x0.y};
                *(float2*)(out0 + o1i) = float2{v2 + b0v + x1.x, v3 + b1v + x1.y};
            }
        }
    }
}

// ===========================================================================
extern "C" void kernel_launch(void* const* d_in, const int* in_sizes, int n_in,
                              void* d_out, int out_size) {
    const float* x   = (const float*)d_in[0];
    const float* d_w = (const float*)d_in[1];
    const float* d_g = (const float*)d_in[2];
    const float* d_b = (const float*)d_in[3];
    const float* p_w = (const float*)d_in[4];
    const float* p_g = (const float*)d_in[5];
    const float* p_b = (const float*)d_in[6];
    const float* w1  = (const float*)d_in[7];
    const float* b1  = (const float*)d_in[8];
    const float* w2  = (const float*)d_in[9];
    const float* b2  = (const float*)d_in[10];
    float* out = (float*)d_out;

    cudaFuncSetAttribute(mma_gemm<1>, cudaFuncAttributeMaxDynamicSharedMemorySize, SMEM_ALLOC);
    cudaFuncSetAttribute(mma_gemm<2>, cudaFuncAttributeMaxDynamicSharedMemorySize, SMEM_ALLOC);
    cudaFuncSetAttribute(mma_gemm<3>, cudaFuncAttributeMaxDynamicSharedMemorySize, SMEM_ALLOC);

    __nv_bfloat16 *xhi, *xlo, *w1hi, *w1lo, *w2hi, *w2lo;
    __nv_bfloat16 *convhi, *convlo, *pwhi, *pwlo, *tmphi, *tmplo;
    cudaGetSymbolAddress((void**)&xhi, g_xhi);
    cudaGetSymbolAddress((void**)&xlo, g_xlo);
    cudaGetSymbolAddress((void**)&w1hi, g_w1hi);
    cudaGetSymbolAddress((void**)&w1lo, g_w1lo);
    cudaGetSymbolAddress((void**)&w2hi, g_w2hi);
    cudaGetSymbolAddress((void**)&w2lo, g_w2lo);
    cudaGetSymbolAddress((void**)&convhi, g_convhi);
    cudaGetSymbolAddress((void**)&convlo, g_convlo);
    cudaGetSymbolAddress((void**)&pwhi, g_pwhi);
    cudaGetSymbolAddress((void**)&pwlo, g_pwlo);
    cudaGetSymbolAddress((void**)&tmphi, g_tmphi);
    cudaGetSymbolAddress((void**)&tmplo, g_tmplo);

    cudaStream_t s2;
    cudaStreamCreateWithFlags(&s2, cudaStreamNonBlocking);
    cudaEvent_t eFork, eDn, ePrep, eG1a, eG1b, eCv1, eCv2, eG2b, eEnd2;
    cudaEventCreateWithFlags(&eFork, cudaEventDisableTiming);
    cudaEventCreateWithFlags(&eDn,   cudaEventDisableTiming);
    cudaEventCreateWithFlags(&ePrep, cudaEventDisableTiming);
    cudaEventCreateWithFlags(&eG1a,  cudaEventDisableTiming);
    cudaEventCreateWithFlags(&eG1b,  cudaEventDisableTiming);
    cudaEventCreateWithFlags(&eCv1,  cudaEventDisableTiming);
    cudaEventCreateWithFlags(&eCv2,  cudaEventDisableTiming);
    cudaEventCreateWithFlags(&eG2b,  cudaEventDisableTiming);
    cudaEventCreateWithFlags(&eEnd2, cudaEventDisableTiming);

    cudaEventRecord(eFork, 0);
    cudaStreamWaitEvent(s2, eFork, 0);

    // s2 (#0): dnorm (needed by conv)
    dnorm_kernel<<<Bq * Kq, 256, 0, s2>>>(d_w);
    cudaEventRecord(eDn, s2);

    // main (#1,#2): x/w1 splits
    split_pack_kernel<<<(Bq * Tq * Dq / 8 + 255) / 256, 256>>>(x, xhi, xlo, 5, 8, Bq * Tq * Dq / 8);
    split_pack_kernel<<<(Cq * Dq / 8 + 255) / 256, 256>>>(w1, w1hi, w1lo, 5, 8, Cq * Dq / 8);

    // main (#3, profiled): GEMM1 half 1 (b 0..7)
    mma_gemm<1><<<dim3(Cq / 128, Tq / 128, BH), 256, SMEM_ALLOC>>>(
        xhi, xlo, Tq / 128, w1hi, w1lo, 0, Dq / 32, 0, b1, nullptr, nullptr);
    cudaEventRecord(eG1a, 0);
    // main: GEMM1 half 2 (b 8..15)
    mma_gemm<1><<<dim3(Cq / 128, Tq / 128, BH), 256, SMEM_ALLOC>>>(
        xhi, xlo, Tq / 128, w1hi, w1lo, 0, Dq / 32, BH, b1, nullptr, nullptr);
    cudaEventRecord(eG1b, 0);

    // s2: remaining prep (overlaps gemm1)
    pnorm_kernel<<<dim3(Bq, Cq / 256), 256, 0, s2>>>(p_w);
    pw_prep_kernel<<<dim3(Cq / 32, Cq / 32, Bq), 256, 0, s2>>>(p_w, p_g);
    split_pack_kernel<<<(Dq * Cq / 8 + 255) / 256, 256, 0, s2>>>(w2, w2hi, w2lo, 7, 32, Dq * Cq / 8);
    cudaEventRecord(ePrep, s2);

    // s2: conv half 1 (needs gemm1_h1 + dnorm; overlaps gemm1_h2)
    cudaStreamWaitEvent(s2, eG1a, 0);
    conv_t_kernel<<<dim3(Cq / 512, Tq / 8, BH), 256, 0, s2>>>(d_w, d_g, d_b, 0);
    cudaEventRecord(eCv1, s2);
    // s2: conv half 2 (needs gemm1_h2; overlaps gemm2_h1 on main)
    cudaStreamWaitEvent(s2, eG1b, 0);
    conv_t_kernel<<<dim3(Cq / 512, Tq / 8, BH), 256, 0, s2>>>(d_w, d_g, d_b, BH);
    cudaEventRecord(eCv2, s2);

    // main chain (half 1): gemm2_h1 -> gemm3_h1
    cudaStreamWaitEvent(0, eCv1, 0);
    cudaStreamWaitEvent(0, ePrep, 0);
    mma_gemm<2><<<dim3(Cq / 128, Tq / 128, BH), 256, SMEM_ALLOC>>>(
        convhi, convlo, Tq / 128, pwhi, pwlo, Cq / 128, Cq / 32, 0, p_b, nullptr, nullptr);
    mma_gemm<3><<<dim3(Dq / 128, Tq / 128, BH), 256, SMEM_ALLOC>>>(
        tmphi, tmplo, Tq / 128, w2hi, w2lo, 0, Cq / 32, 0, b2, x, out);

    // s2 chain (half 2, concurrent with half-1 chain): gemm2_h2 -> gemm3_h2
    cudaStreamWaitEvent(s2, eCv2, 0);   // ePrep already ordered on s2
    mma_gemm<2><<<dim3(Cq / 128, Tq / 128, BH), 256, SMEM_ALLOC, s2>>>(
        convhi, convlo, Tq / 128, pwhi, pwlo, Cq / 128, Cq / 32, BH, p_b, nullptr, nullptr);
    mma_gemm<3><<<dim3(Dq / 128, Tq / 128, BH), 256, SMEM_ALLOC, s2>>>(
        tmphi, tmplo, Tq / 128, w2hi, w2lo, 0, Cq / 32, BH, b2, x, out);
    cudaEventRecord(eEnd2, s2);

    // Join: main stream must not complete before s2's half-2 chain.
    cudaStreamWaitEvent(0, eEnd2, 0);
}

// round 14
// speedup vs baseline: 1.0527x; 1.0527x over previous
#include <cuda_runtime.h>
#include <cuda_bf16.h>
#include <cstdint>
#include <math.h>

#define Bq  16
#define Tq  1024
#define Dq  256
#define Cq  1024
#define Kq  9

// ===========================================================================
// Helpers (baseline PTX only — no 'a'-suffix features)
// ===========================================================================
__device__ __forceinline__ uint32_t smem_to_u32(const void* p) {
    uint32_t a;
    asm("{ .reg .u64 t; cvta.to.shared.u64 t, %1; cvt.u32.u64 %0, t; }" : "=r"(a) : "l"(p));
    return a;
}
#define LDSM_X4(r, a) \
    asm volatile("ldmatrix.sync.aligned.m8n8.x4.shared.b16 {%0,%1,%2,%3}, [%4];" \
        : "=r"((r)[0]), "=r"((r)[1]), "=r"((r)[2]), "=r"((r)[3]) : "r"(a))
#define MMA_BF16(d, a, bb) \
    asm volatile("mma.sync.aligned.m16n8k16.row.col.f32.bf16.bf16.f32 " \
        "{%0,%1,%2,%3}, {%4,%5,%6,%7}, {%8,%9}, {%0,%1,%2,%3};" \
        : "+f"((d)[0]), "+f"((d)[1]), "+f"((d)[2]), "+f"((d)[3]) \
        : "r"((a)[0]), "r"((a)[1]), "r"((a)[2]), "r"((a)[3]), \
          "r"((bb)[0]), "r"((bb)[1]))

#define MBARRIER_INIT(mb, c) \
    asm volatile("mbarrier.init.shared.b64 [%0], %1;" :: "r"((uint32_t)(mb)), "r"((uint32_t)(c)) : "memory")
#define MBARRIER_WAIT_PARITY(mb, ph) do { \
    uint32_t _m = (uint32_t)(mb); uint32_t _p = (uint32_t)(ph); uint32_t _d; \
    asm volatile("{\n\t.reg .pred p;\n\t" \
        "mbarrier.try_wait.parity.acquire.cta.shared::cta.b64 p, [%1], %2;\n\t" \
        "selp.b32 %0, 1, 0, p;\n\t}" : "=r"(_d) : "r"(_m), "r"(_p) : "memory"); \
    if (!_d) { \
        asm volatile("{\n\t.reg .pred P1;\n\t" \
            "WL_%=:\n\t" \
            "mbarrier.try_wait.parity.acquire.cta.shared::cta.b64 P1, [%0], %1, 0x989680;\n\t" \
            "@P1 bra.uni WD_%=;\n\t" \
            "bra.uni WL_%=;\n\t" \
            "WD_%=:\n\t}" :: "r"(_m), "r"(_p) : "memory"); \
    } } while (0)

// Named-barrier producer/consumer: warps 1..7 arrive (non-blocking),
// warp 0 syncs (blocks until all 256 arrivals) before refilling the buffer.
#define BAR_ARRIVE(id) asm volatile("bar.arrive %0, 256;" :: "r"(id) : "memory")
#define BAR_SYNC(id)   asm volatile("bar.sync %0, 256;"   :: "r"(id) : "memory")

__device__ __forceinline__ void bulk_ld(uint32_t dst, const void* src, uint32_t mb) {
    asm volatile(
        "cp.async.bulk.shared::cta.global.mbarrier::complete_tx::bytes [%0], [%1], %2, [%3];"
        :: "r"(dst), "l"(src), "r"(8192u), "r"(mb) : "memory");
}
__device__ __forceinline__ void mbar_expect(uint32_t mb, uint32_t bytes) {
    asm volatile("mbarrier.arrive.expect_tx.shared.b64 _, [%0], %1;"
        :: "r"(mb), "r"(bytes) : "memory");
}

// mish(x) = x * w / (w + 2),  w = e^x (e^x + 2). Branch-free: clamp exp at 15
// (tanh(softplus(15)) = 1 - 2e-13); x -> -inf gives w -> 0 -> result 0.
__device__ __forceinline__ float mishf(float x) {
    float t = __expf(fminf(x, 15.f));
    float w = t * (t + 2.f);
    return x * __fdividef(w, w + 2.f);
}
__device__ __forceinline__ void bsplit(float v, __nv_bfloat16& h, __nv_bfloat16& l) {
    h = __float2bfloat16(v);
    l = __float2bfloat16(v - __bfloat162float(h));
}
__device__ __forceinline__ uint32_t pkbf(__nv_bfloat16 a, __nv_bfloat16 b) {
    __nv_bfloat162 t{a, b};
    return *(uint32_t*)&t;
}

// Packed layout: matrix [R rows][K cols] bf16 -> blocks of 128 rows x 32 k
// (8192 B, chunk-contiguous). Within block: phys row p = r>>1 (128 B),
// 16B segment index = (((r&1)<<2)|s) ^ (p&7), s = (k%32)>>3.
__device__ __forceinline__ size_t pk_off(int m, int q, int r, int s, int nq) {
    int p = r >> 1;
    int seg = ((((r & 1) << 2) | s) ^ (p & 7));
    return ((size_t)(m * nq + q) << 13) + ((size_t)p << 7) + ((size_t)seg << 4);
}

// ===========================================================================
// Device scratch
// ===========================================================================
__device__ __align__(16) __nv_bfloat16 g_xhi[(size_t)Bq * Tq * Dq];     // packed
__device__ __align__(16) __nv_bfloat16 g_xlo[(size_t)Bq * Tq * Dq];
__device__ __align__(16) __nv_bfloat16 g_w1hi[(size_t)Cq * Dq];         // packed
__device__ __align__(16) __nv_bfloat16 g_w1lo[(size_t)Cq * Dq];
__device__ __align__(16) __nv_bfloat16 g_w2hi[(size_t)Dq * Cq];         // packed
__device__ __align__(16) __nv_bfloat16 g_w2lo[(size_t)Dq * Cq];
__device__ __align__(16) float g_hT[(size_t)Bq * Tq * Cq];              // plain [b][t][c]
__device__ __align__(16) __nv_bfloat16 g_convhi[(size_t)Bq * Tq * Cq];  // packed
__device__ __align__(16) __nv_bfloat16 g_convlo[(size_t)Bq * Tq * Cq];
__device__ __align__(16) __nv_bfloat16 g_pwhi[(size_t)Bq * Cq * Cq];    // packed
__device__ __align__(16) __nv_bfloat16 g_pwlo[(size_t)Bq * Cq * Cq];
__device__ __align__(16) __nv_bfloat16 g_tmphi[(size_t)Bq * Tq * Cq];   // packed
__device__ __align__(16) __nv_bfloat16 g_tmplo[(size_t)Bq * Tq * Cq];
__device__ float g_inv_pnorm[Bq * Cq];
__device__ float g_inv_dnorm[Bq * Kq];

// ===========================================================================
// Prep kernels
// ===========================================================================
__global__ void split_pack_kernel(const float* __restrict__ src,
                                  __nv_bfloat16* __restrict__ hi,
                                  __nv_bfloat16* __restrict__ lo,
                                  int lgspr, int nq, int total) {
    int idx = blockIdx.x * 256 + threadIdx.x;
    if (idx >= total) return;
    int spr = 1 << lgspr;
    int r_all = idx >> lgspr;
    int kseg = idx & (spr - 1);
    int q = kseg >> 2, s = kseg & 3;
    int m = r_all >> 7, r = r_all & 127;
    const float* sp = src + ((size_t)r_all << (lgspr + 3)) + ((size_t)kseg << 3);
    float4 v0 = *(const float4*)sp;
    float4 v1 = *(const float4*)(sp + 4);
    __nv_bfloat16 h[8], l[8];
    bsplit(v0.x, h[0], l[0]); bsplit(v0.y, h[1], l[1]);
    bsplit(v0.z, h[2], l[2]); bsplit(v0.w, h[3], l[3]);
    bsplit(v1.x, h[4], l[4]); bsplit(v1.y, h[5], l[5]);
    bsplit(v1.z, h[6], l[6]); bsplit(v1.w, h[7], l[7]);
    size_t off = pk_off(m, q, r, s, nq);
    uint4 hv = make_uint4(pkbf(h[0],h[1]), pkbf(h[2],h[3]), pkbf(h[4],h[5]), pkbf(h[6],h[7]));
    uint4 lv = make_uint4(pkbf(l[0],l[1]), pkbf(l[2],l[3]), pkbf(l[4],l[5]), pkbf(l[6],l[7]));
    *(uint4*)((char*)hi + off) = hv;
    *(uint4*)((char*)lo + off) = lv;
}

__global__ void dnorm_kernel(const float* __restrict__ d_w) {
    int bk = blockIdx.x;
    int b = bk / Kq, k = bk % Kq;
    float s = 0.f;
    for (int c = threadIdx.x; c < Cq; c += 256) {
        float v = d_w[((size_t)b * Cq + c) * Kq + k];
        s = fmaf(v, v, s);
    }
    __shared__ float red[256];
    red[threadIdx.x] = s;
    __syncthreads();
    for (int off = 128; off > 0; off >>= 1) {
        if (threadIdx.x < off) red[threadIdx.x] += red[threadIdx.x + off];
        __syncthreads();
    }
    if (threadIdx.x == 0)
        g_inv_dnorm[bk] = 1.f / fmaxf(sqrtf(red[0]), 1e-12f);
}

__global__ void pnorm_kernel(const float* __restrict__ p_w) {
    int b = blockIdx.x;
    int o = blockIdx.y * 256 + threadIdx.x;
    const float* base = p_w + (size_t)b * Cq * Cq + o;
    float s = 0.f;
    #pragma unroll 4
    for (int c = 0; c < Cq; ++c) {
        float v = base[(size_t)c * Cq];
        s = fmaf(v, v, s);
    }
    g_inv_pnorm[b * Cq + o] = 1.f / fmaxf(sqrtf(s), 1e-12f);
}

// Transpose p_w[b][c][o]*p_g[b][c] -> packed [b*1024+o rows][c cols] bf16 split
__global__ __launch_bounds__(256) void pw_prep_kernel(
    const float* __restrict__ p_w, const float* __restrict__ p_g) {
    int b = blockIdx.z;
    int c0 = blockIdx.x * 32;
    int o0 = blockIdx.y * 32;
    __shared__ float s[32][33];
    __shared__ float pgs[32];
    int tid = threadIdx.x;
    int x = tid & 31, y = tid >> 5;
    if (tid < 32) pgs[tid] = p_g[b * Cq + c0 + tid];
    const float* in = p_w + (size_t)b * Cq * Cq;
    #pragma unroll
    for (int yy = 0; yy < 4; ++yy) {
        int c = c0 + y * 4 + yy;
        s[y * 4 + yy][x] = in[(size_t)c * Cq + o0 + x];
    }
    __syncthreads();
    int q = c0 >> 5;
    int sseg = x >> 3;
    int ins = (x & 7) << 1;
    #pragma unroll
    for (int yy = 0; yy < 4; ++yy) {
        int o = o0 + y * 4 + yy;
        float w = s[x][y * 4 + yy] * pgs[x];
        __nv_bfloat16 h, l;
        bsplit(w, h, l);
        int m = (b << 3) | (o >> 7);
        size_t off = pk_off(m, q, o & 127, sseg, 32) + ins;
        *(__nv_bfloat16*)((char*)g_pwhi + off) = h;
        *(__nv_bfloat16*)((char*)g_pwlo + off) = l;
    }
}

// ===========================================================================
// Depthwise conv on [t][c] layout -> packed bf16 split
// ===========================================================================
__global__ __launch_bounds__(256) void conv_t_kernel(
    const float* __restrict__ d_w, const float* __restrict__ d_g,
    const float* __restrict__ d_b) {
    int b  = blockIdx.z;
    int t0 = blockIdx.y * 8;
    int ch = blockIdx.x * 512;
    __shared__ float s[16][512];
    const float* h = g_hT + (size_t)b * Tq * Cq;
    int tid = threadIdx.x;
    #pragma unroll
    for (int i = 0; i < 8; ++i) {
        int idx = tid + i * 256;
        int r  = idx >> 7;
        int cc = (idx & 127) * 4;
        int t = t0 - 4 + r;
        float4 v = (t >= 0 && t < Tq)
            ? *(const float4*)(h + (size_t)t * Cq + ch + cc)
            : make_float4(0.f, 0.f, 0.f, 0.f);
        *(float4*)&s[r][cc] = v;
    }
    __syncthreads();
    int cg = (tid & 127) * 4;
    int tsub = tid >> 7;
    int c = ch + cg;
    float w[Kq][4], bias[4];
    #pragma unroll
    for (int qd = 0; qd < 4; ++qd) {
        float g = d_g[b * Cq + c + qd];
        bias[qd] = d_b[b * Cq + c + qd];
        #pragma unroll
        for (int k = 0; k < Kq; ++k)
            w[k][qd] = d_w[((size_t)b * Cq + c + qd) * Kq + k] * g_inv_dnorm[b * Kq + k] * g;
    }
    int qc = c >> 5;
    int sc = (c >> 3) & 3;
    int ins = (c & 7) << 1;
    #pragma unroll
    for (int i = 0; i < 4; ++i) {
        int tl = tsub * 4 + i;
        int t = t0 + tl;
        float4 acc = make_float4(bias[0], bias[1], bias[2], bias[3]);
        #pragma unroll
        for (int k = 0; k < Kq; ++k) {
            float4 vv = *(float4*)&s[tl + k][cg];
            acc.x = fmaf(vv.x, w[k][0], acc.x);
            acc.y = fmaf(vv.y, w[k][1], acc.y);
            acc.z = fmaf(vv.z, w[k][2], acc.z);
            acc.w = fmaf(vv.w, w[k][3], acc.w);
        }
        __nv_bfloat16 h0, h1, h2, h3, l0, l1, l2, l3;
        bsplit(acc.x, h0, l0); bsplit(acc.y, h1, l1);
        bsplit(acc.z, h2, l2); bsplit(acc.w, h3, l3);
        int m = (b << 3) | (t >> 7);
        size_t off = pk_off(m, qc, t & 127, sc, 32) + ins;
        *(uint2*)((char*)g_convhi + off) = make_uint2(pkbf(h0,h1), pkbf(h2,h3));
        *(uint2*)((char*)g_convlo + off) = make_uint2(pkbf(l0,l1), pkbf(l2,l3));
    }
}

// ===========================================================================
// mma.sync bf16-split GEMM with cp.async.bulk chunk loads.
// CTA tile 128x128, K-chunk 32, 2 stages x 32KB, 2 CTAs/SM.
// Decoupled sync: consumers bar.arrive per chunk (non-blocking); only warp 0
// bar.syncs before refilling. Two barrier IDs alternate by buffer parity.
// ===========================================================================
#define STAGE_B 32768
#define SMEM_ALLOC (1024 + 128 + 2 * STAGE_B)

__device__ __forceinline__ void issue_chunk(uint32_t st0, uint32_t mbf,
    const char* Ah, const char* Al, const char* Bh, const char* Bl, int q) {
    int buf = q & 1;
    uint32_t mb = mbf + (uint32_t)buf * 8u;
    uint32_t dst = st0 + (uint32_t)buf * STAGE_B;
    size_t qo = (size_t)q << 13;
    mbar_expect(mb, 32768u);
    bulk_ld(dst,          Ah + qo, mb);
    bulk_ld(dst + 8192u,  Al + qo, mb);
    bulk_ld(dst + 16384u, Bh + qo, mb);
    bulk_ld(dst + 24576u, Bl + qo, mb);
}

template <int EPI>
__global__ __launch_bounds__(256, 2) void mma_gemm(
    const __nv_bfloat16* __restrict__ Ahi, const __nv_bfloat16* __restrict__ Alo,
    int a_mpb,
    const __nv_bfloat16* __restrict__ Bhi, const __nv_bfloat16* __restrict__ Blo,
    int b_mpb,
    int nchunks,
    const float* __restrict__ e0, const float* __restrict__ e1,
    float* __restrict__ out0) {
    extern __shared__ __align__(128) char dsm[];
    uint32_t raw = smem_to_u32(dsm);
    uint32_t hdr = (raw + 1023u) & ~1023u;
    uint32_t mbf = hdr;
    uint32_t st0 = hdr + 128;
    int tid = threadIdx.x;
    int wid = tid >> 5, lane = tid & 31;
    int wm = wid >> 2, wn = wid & 3;
    int b = blockIdx.z, m0 = blockIdx.y * 128, n0 = blockIdx.x * 128;

    const char* Abh = (const char*)Ahi + ((size_t)((b * a_mpb + blockIdx.y) * nchunks) << 13);
    const char* Abl = (const char*)Alo + ((size_t)((b * a_mpb + blockIdx.y) * nchunks) << 13);
    const char* Bbh = (const char*)Bhi + ((size_t)((b * b_mpb + blockIdx.x) * nchunks) << 13);
    const char* Bbl = (const char*)Blo + ((size_t)((b * b_mpb + blockIdx.x) * nchunks) << 13);

    if (tid == 0) {
        MBARRIER_INIT(mbf, 1);
        MBARRIER_INIT(mbf + 8, 1);
    }
    __syncthreads();
    if (tid == 0) {
        issue_chunk(st0, mbf, Abh, Abl, Bbh, Bbl, 0);
        issue_chunk(st0, mbf, Abh, Abl, Bbh, Bbl, 1);
    }

    uint32_t aoff[4][2], boff4[2][2];
    {
        int rla = lane & 15, sha = (lane >> 4) & 1;
        #pragma unroll
        for (int i = 0; i < 4; ++i) {
            int r = wm * 64 + i * 16 + rla;
            int p = r >> 1, x4 = (r & 1) << 2, mk = p & 7, rb = p << 7;
            aoff[i][0] = rb + (((x4 | sha) ^ mk) << 4);
            aoff[i][1] = rb + (((x4 | (2 + sha)) ^ mk) << 4);
        }
        int rlb = lane & 7;
        int shb = (lane >> 3) & 1;
        int jsel = (lane >> 4) & 1;
        #pragma unroll
        for (int J = 0; J < 2; ++J) {
            int r = wn * 32 + (J * 2 + jsel) * 8 + rlb;
            int p = r >> 1, x4 = (r & 1) << 2, mk = p & 7, rb = p << 7;
            boff4[J][0] = rb + (((x4 | shb) ^ mk) << 4);
            boff4[J][1] = rb + (((x4 | (2 + shb)) ^ mk) << 4);
        }
    }

    float acc[4][4][4] = {};

    for (int q = 0; q < nchunks; ++q) {
        int buf = q & 1;
        MBARRIER_WAIT_PARITY(mbf + (uint32_t)buf * 8u, (q >> 1) & 1);
        uint32_t st = st0 + (uint32_t)buf * STAGE_B;
        #pragma unroll
        for (int ks = 0; ks < 2; ++ks) {
            uint32_t ah[4][4], al[4][4], bh[4][2], bl[4][2];
            #pragma unroll
            for (int J = 0; J < 2; ++J) {
                LDSM_X4(&bh[J * 2][0], st + 16384u + boff4[J][ks]);
                LDSM_X4(&bl[J * 2][0], st + 24576u + boff4[J][ks]);
            }
            #pragma unroll
            for (int i = 0; i < 4; ++i)
                LDSM_X4(ah[i], st + aoff[i][ks]);
            #pragma unroll
            for (int i = 0; i < 4; ++i)
                #pragma unroll
                for (int jj = 0; jj < 4; ++jj)
                    MMA_BF16(acc[i][jj], ah[i], bh[jj]);
            #pragma unroll
            for (int i = 0; i < 4; ++i)
                LDSM_X4(al[i], st + 8192u + aoff[i][ks]);
            #pragma unroll
            for (int i = 0; i < 4; ++i)
                #pragma unroll
                for (int jj = 0; jj < 4; ++jj)
                    MMA_BF16(acc[i][jj], ah[i], bl[jj]);
            #pragma unroll
            for (int i = 0; i < 4; ++i)
                #pragma unroll
                for (int jj = 0; jj < 4; ++jj)
                    MMA_BF16(acc[i][jj], al[i], bh[jj]);
        }
        // Decoupled release: consumers signal done-with-buf and move on;
        // producer (warp 0) waits for all, then refills.
        if (q + 2 < nchunks) {
            int barid = 1 + buf;
            if (wid != 0) {
                BAR_ARRIVE(barid);
            } else {
                BAR_SYNC(barid);
                if (tid == 0)
                    issue_chunk(st0, mbf, Abh, Abl, Bbh, Bbl, q + 2);
            }
        }
    }

    int gid = lane >> 2, tig = lane & 3;
    #pragma unroll
    for (int i = 0; i < 4; ++i) {
        int r0 = m0 + wm * 64 + i * 16 + gid;
        #pragma unroll
        for (int jj = 0; jj < 4; ++jj) {
            int col = n0 + wn * 32 + jj * 8 + tig * 2;
            float v0 = acc[i][jj][0], v1 = acc[i][jj][1];
            float v2 = acc[i][jj][2], v3 = acc[i][jj][3];
            if (EPI == 1) {
                float b0v = e0[col], b1v = e0[col + 1];
                float* d0 = g_hT + ((size_t)b * Tq + r0) * Cq + col;
                float* d1 = g_hT + ((size_t)b * Tq + r0 + 8) * Cq + col;
                *(float2*)d0 = float2{mishf(v0 + b0v), mishf(v1 + b1v)};
                *(float2*)d1 = float2{mishf(v2 + b0v), mishf(v3 + b1v)};
            } else if (EPI == 2) {
                float s0 = g_inv_pnorm[b * Cq + col], s1 = g_inv_pnorm[b * Cq + col + 1];
                float p0 = e0[b * Cq + col], p1 = e0[b * Cq + col + 1];
                float u0 = mishf(fmaf(v0, s0, p0)), u1 = mishf(fmaf(v1, s1, p1));
                float u2 = mishf(fmaf(v2, s0, p0)), u3 = mishf(fmaf(v3, s1, p1));
                __nv_bfloat16 h0, h1, h2, h3, l0, l1, l2, l3;
                bsplit(u0, h0, l0); bsplit(u1, h1, l1);
                bsplit(u2, h2, l2); bsplit(u3, h3, l3);
                int m = (b << 3) | (r0 >> 7);
                int qp = col >> 5, sp = (col >> 3) & 3, ins = (col & 7) << 1;
                size_t oA = pk_off(m, qp, r0 & 127, sp, 32) + ins;
                size_t oB = pk_off(m, qp, (r0 + 8) & 127, sp, 32) + ins;
                *(uint32_t*)((char*)g_tmphi + oA) = pkbf(h0, h1);
                *(uint32_t*)((char*)g_tmphi + oB) = pkbf(h2, h3);
                *(uint32_t*)((char*)g_tmplo + oA) = pkbf(l0, l1);
                *(uint32_t*)((char*)g_tmplo + oB) = pkbf(l2, l3);
            } else {
                float b0v = e0[col], b1v = e0[col + 1];
                size_t o0i = ((size_t)b * Tq + r0) * Dq + col;
                size_t o1i = ((size_t)b * Tq + r0 + 8) * Dq + col;
                float2 x0 = *(const float2*)(e1 + o0i);
                float2 x1 = *(const float2*)(e1 + o1i);
                *(float2*)(out0 + o0i) = float2{v0 + b0v + x0.x, v1 + b1v + x0.y};
                *(float2*)(out0 + o1i) = float2{v2 + b0v + x1.x, v3 + b1v + x1.y};
            }
        }
    }
}

// ===========================================================================
extern "C" void kernel_launch(void* const* d_in, const int* in_sizes, int n_in,
                              void* d_out, int out_size) {
    const float* x   = (const float*)d_in[0];
    const float* d_w = (const float*)d_in[1];
    const float* d_g = (const float*)d_in[2];
    const float* d_b = (const float*)d_in[3];
    const float* p_w = (const float*)d_in[4];
    const float* p_g = (const float*)d_in[5];
    const float* p_b = (const float*)d_in[6];
    const float* w1  = (const float*)d_in[7];
    const float* b1  = (const float*)d_in[8];
    const float* w2  = (const float*)d_in[9];
    const float* b2  = (const float*)d_in[10];
    float* out = (float*)d_out;

    cudaFuncSetAttribute(mma_gemm<1>, cudaFuncAttributeMaxDynamicSharedMemorySize, SMEM_ALLOC);
    cudaFuncSetAttribute(mma_gemm<2>, cudaFuncAttributeMaxDynamicSharedMemorySize, SMEM_ALLOC);
    cudaFuncSetAttribute(mma_gemm<3>, cudaFuncAttributeMaxDynamicSharedMemorySize, SMEM_ALLOC);

    __nv_bfloat16 *xhi, *xlo, *w1hi, *w1lo, *w2hi, *w2lo;
    __nv_bfloat16 *convhi, *convlo, *pwhi, *pwlo, *tmphi, *tmplo;
    cudaGetSymbolAddress((void**)&xhi, g_xhi);
    cudaGetSymbolAddress((void**)&xlo, g_xlo);
    cudaGetSymbolAddress((void**)&w1hi, g_w1hi);
    cudaGetSymbolAddress((void**)&w1lo, g_w1lo);
    cudaGetSymbolAddress((void**)&w2hi, g_w2hi);
    cudaGetSymbolAddress((void**)&w2lo, g_w2lo);
    cudaGetSymbolAddress((void**)&convhi, g_convhi);
    cudaGetSymbolAddress((void**)&convlo, g_convlo);
    cudaGetSymbolAddress((void**)&pwhi, g_pwhi);
    cudaGetSymbolAddress((void**)&pwlo, g_pwlo);
    cudaGetSymbolAddress((void**)&tmphi, g_tmphi);
    cudaGetSymbolAddress((void**)&tmplo, g_tmplo);

    // Fork a side stream into the capture for independent prep work.
    cudaStream_t s2;
    cudaStreamCreateWithFlags(&s2, cudaStreamNonBlocking);
    cudaEvent_t eFork, eDn, eJoin;
    cudaEventCreateWithFlags(&eFork, cudaEventDisableTiming);
    cudaEventCreateWithFlags(&eDn,   cudaEventDisableTiming);
    cudaEventCreateWithFlags(&eJoin, cudaEventDisableTiming);

    cudaEventRecord(eFork, 0);
    cudaStreamWaitEvent(s2, eFork, 0);

    // Submission order puts gemm1 at index 3 for ncu.
    dnorm_kernel<<<Bq * Kq, 256, 0, s2>>>(d_w);                                   // #0
    cudaEventRecord(eDn, s2);
    split_pack_kernel<<<(Bq * Tq * Dq / 8 + 255) / 256, 256>>>(x, xhi, xlo, 5, 8, Bq * Tq * Dq / 8); // #1
    split_pack_kernel<<<(Cq * Dq / 8 + 255) / 256, 256>>>(w1, w1hi, w1lo, 5, 8, Cq * Dq / 8);        // #2

    // GEMM1 (#3, profiled): h = mish(x @ w1^T + b1)
    mma_gemm<1><<<dim3(Cq / 128, Tq / 128, Bq), 256, SMEM_ALLOC>>>(
        xhi, xlo, Tq / 128, w1hi, w1lo, 0, Dq / 32, b1, nullptr, nullptr);

    // Side stream (concurrent with gemm1 on-device).
    pnorm_kernel<<<dim3(Bq, Cq / 256), 256, 0, s2>>>(p_w);
    pw_prep_kernel<<<dim3(Cq / 32, Cq / 32, Bq), 256, 0, s2>>>(p_w, p_g);
    split_pack_kernel<<<(Dq * Cq / 8 + 255) / 256, 256, 0, s2>>>(w2, w2hi, w2lo, 7, 32, Dq * Cq / 8);
    cudaEventRecord(eJoin, s2);

    cudaStreamWaitEvent(0, eDn, 0);
    conv_t_kernel<<<dim3(Cq / 512, Tq / 8, Bq), 256>>>(d_w, d_g, d_b);

    cudaStreamWaitEvent(0, eJoin, 0);
    // GEMM2: tmp = mish(inv_pnorm*(conv @ pw^T) + p_b)
    mma_gemm<2><<<dim3(Cq / 128, Tq / 128, Bq), 256, SMEM_ALLOC>>>(
        convhi, convlo, Tq / 128, pwhi, pwlo, Cq / 128, Cq / 32, p_b, nullptr, nullptr);

    // GEMM3: out = tmp @ w2^T + b2 + x
    mma_gemm<3><<<dim3(Dq / 128, Tq / 128, Bq), 256, SMEM_ALLOC>>>(
        tmphi, tmplo, Tq / 128, w2hi, w2lo, 0, Cq / 32, b2, x, out);
}

// round 15
// speedup vs baseline: 1.0800x; 1.0259x over previous
#include <cuda_runtime.h>
#include <cuda_bf16.h>
#include <cstdint>
#include <math.h>

#define Bq  16
#define Tq  1024
#define Dq  256
#define Cq  1024
#define Kq  9

// ===========================================================================
// Helpers (baseline PTX only — no 'a'-suffix features)
// ===========================================================================
__device__ __forceinline__ uint32_t smem_to_u32(const void* p) {
    uint32_t a;
    asm("{ .reg .u64 t; cvta.to.shared.u64 t, %1; cvt.u32.u64 %0, t; }" : "=r"(a) : "l"(p));
    return a;
}
#define LDSM_X4(r, a) \
    asm volatile("ldmatrix.sync.aligned.m8n8.x4.shared.b16 {%0,%1,%2,%3}, [%4];" \
        : "=r"((r)[0]), "=r"((r)[1]), "=r"((r)[2]), "=r"((r)[3]) : "r"(a))
#define MMA_BF16(d, a, bb) \
    asm volatile("mma.sync.aligned.m16n8k16.row.col.f32.bf16.bf16.f32 " \
        "{%0,%1,%2,%3}, {%4,%5,%6,%7}, {%8,%9}, {%0,%1,%2,%3};" \
        : "+f"((d)[0]), "+f"((d)[1]), "+f"((d)[2]), "+f"((d)[3]) \
        : "r"((a)[0]), "r"((a)[1]), "r"((a)[2]), "r"((a)[3]), \
          "r"((bb)[0]), "r"((bb)[1]))

#define MBARRIER_INIT(mb, c) \
    asm volatile("mbarrier.init.shared.b64 [%0], %1;" :: "r"((uint32_t)(mb)), "r"((uint32_t)(c)) : "memory")
#define MBARRIER_WAIT_PARITY(mb, ph) do { \
    uint32_t _m = (uint32_t)(mb); uint32_t _p = (uint32_t)(ph); uint32_t _d; \
    asm volatile("{\n\t.reg .pred p;\n\t" \
        "mbarrier.try_wait.parity.acquire.cta.shared::cta.b64 p, [%1], %2;\n\t" \
        "selp.b32 %0, 1, 0, p;\n\t}" : "=r"(_d) : "r"(_m), "r"(_p) : "memory"); \
    if (!_d) { \
        asm volatile("{\n\t.reg .pred P1;\n\t" \
            "WL_%=:\n\t" \
            "mbarrier.try_wait.parity.acquire.cta.shared::cta.b64 P1, [%0], %1, 0x989680;\n\t" \
            "@P1 bra.uni WD_%=;\n\t" \
            "bra.uni WL_%=;\n\t" \
            "WD_%=:\n\t}" :: "r"(_m), "r"(_p) : "memory"); \
    } } while (0)

// Named-barrier producer/consumer: warps 1..7 arrive (non-blocking),
// warp 0 syncs (blocks until all 256 arrivals) before refilling the buffer.
#define BAR_ARRIVE(id) asm volatile("bar.arrive %0, 256;" :: "r"(id) : "memory")
#define BAR_SYNC(id)   asm volatile("bar.sync %0, 256;"   :: "r"(id) : "memory")

__device__ __forceinline__ void bulk_ld(uint32_t dst, const void* src, uint32_t mb) {
    asm volatile(
        "cp.async.bulk.shared::cta.global.mbarrier::complete_tx::bytes [%0], [%1], %2, [%3];"
        :: "r"(dst), "l"(src), "r"(8192u), "r"(mb) : "memory");
}
__device__ __forceinline__ void mbar_expect(uint32_t mb, uint32_t bytes) {
    asm volatile("mbarrier.arrive.expect_tx.shared.b64 _, [%0], %1;"
        :: "r"(mb), "r"(bytes) : "memory");
}

// mish(x) = x * w / (w + 2),  w = e^x (e^x + 2). Branch-free: clamp exp at 15.
__device__ __forceinline__ float mishf(float x) {
    float t = __expf(fminf(x, 15.f));
    float w = t * (t + 2.f);
    return x * __fdividef(w, w + 2.f);
}
__device__ __forceinline__ void bsplit(float v, __nv_bfloat16& h, __nv_bfloat16& l) {
    h = __float2bfloat16(v);
    l = __float2bfloat16(v - __bfloat162float(h));
}
__device__ __forceinline__ uint32_t pkbf(__nv_bfloat16 a, __nv_bfloat16 b) {
    __nv_bfloat162 t{a, b};
    return *(uint32_t*)&t;
}

// Packed layout: matrix [R rows][K cols] bf16 -> blocks of 128 rows x 32 k
// (8192 B, chunk-contiguous). Within block: phys row p = r>>1 (128 B),
// 16B segment index = (((r&1)<<2)|s) ^ (p&7), s = (k%32)>>3.
__device__ __forceinline__ size_t pk_off(int m, int q, int r, int s, int nq) {
    int p = r >> 1;
    int seg = ((((r & 1) << 2) | s) ^ (p & 7));
    return ((size_t)(m * nq + q) << 13) + ((size_t)p << 7) + ((size_t)seg << 4);
}

// ===========================================================================
// Device scratch
// ===========================================================================
__device__ __align__(16) __nv_bfloat16 g_xhi[(size_t)Bq * Tq * Dq];     // packed
__device__ __align__(16) __nv_bfloat16 g_xlo[(size_t)Bq * Tq * Dq];
__device__ __align__(16) __nv_bfloat16 g_w1hi[(size_t)Cq * Dq];         // packed
__device__ __align__(16) __nv_bfloat16 g_w1lo[(size_t)Cq * Dq];
__device__ __align__(16) __nv_bfloat16 g_w2hi[(size_t)Dq * Cq];         // packed
__device__ __align__(16) __nv_bfloat16 g_w2lo[(size_t)Dq * Cq];
__device__ __align__(16) float g_hT[(size_t)Bq * Tq * Cq];              // plain [b][t][c]
__device__ __align__(16) __nv_bfloat16 g_convhi[(size_t)Bq * Tq * Cq];  // packed
__device__ __align__(16) __nv_bfloat16 g_convlo[(size_t)Bq * Tq * Cq];
__device__ __align__(16) __nv_bfloat16 g_pwhi[(size_t)Bq * Cq * Cq];    // packed
__device__ __align__(16) __nv_bfloat16 g_pwlo[(size_t)Bq * Cq * Cq];
__device__ __align__(16) __nv_bfloat16 g_tmphi[(size_t)Bq * Tq * Cq];   // packed
__device__ __align__(16) __nv_bfloat16 g_tmplo[(size_t)Bq * Tq * Cq];
__device__ float g_inv_pnorm[Bq * Cq];
__device__ float g_inv_dnorm[Bq * Kq];

// ===========================================================================
// Prep kernels
// ===========================================================================
__global__ void split_pack_kernel(const float* __restrict__ src,
                                  __nv_bfloat16* __restrict__ hi,
                                  __nv_bfloat16* __restrict__ lo,
                                  int lgspr, int nq, int total) {
    int idx = blockIdx.x * 256 + threadIdx.x;
    if (idx >= total) return;
    int spr = 1 << lgspr;
    int r_all = idx >> lgspr;
    int kseg = idx & (spr - 1);
    int q = kseg >> 2, s = kseg & 3;
    int m = r_all >> 7, r = r_all & 127;
    const float* sp = src + ((size_t)r_all << (lgspr + 3)) + ((size_t)kseg << 3);
    float4 v0 = *(const float4*)sp;
    float4 v1 = *(const float4*)(sp + 4);
    __nv_bfloat16 h[8], l[8];
    bsplit(v0.x, h[0], l[0]); bsplit(v0.y, h[1], l[1]);
    bsplit(v0.z, h[2], l[2]); bsplit(v0.w, h[3], l[3]);
    bsplit(v1.x, h[4], l[4]); bsplit(v1.y, h[5], l[5]);
    bsplit(v1.z, h[6], l[6]); bsplit(v1.w, h[7], l[7]);
    size_t off = pk_off(m, q, r, s, nq);
    uint4 hv = make_uint4(pkbf(h[0],h[1]), pkbf(h[2],h[3]), pkbf(h[4],h[5]), pkbf(h[6],h[7]));
    uint4 lv = make_uint4(pkbf(l[0],l[1]), pkbf(l[2],l[3]), pkbf(l[4],l[5]), pkbf(l[6],l[7]));
    *(uint4*)((char*)hi + off) = hv;
    *(uint4*)((char*)lo + off) = lv;
}

__global__ void dnorm_kernel(const float* __restrict__ d_w) {
    int bk = blockIdx.x;
    int b = bk / Kq, k = bk % Kq;
    float s = 0.f;
    for (int c = threadIdx.x; c < Cq; c += 256) {
        float v = d_w[((size_t)b * Cq + c) * Kq + k];
        s = fmaf(v, v, s);
    }
    __shared__ float red[256];
    red[threadIdx.x] = s;
    __syncthreads();
    for (int off = 128; off > 0; off >>= 1) {
        if (threadIdx.x < off) red[threadIdx.x] += red[threadIdx.x + off];
        __syncthreads();
    }
    if (threadIdx.x == 0)
        g_inv_dnorm[bk] = 1.f / fmaxf(sqrtf(red[0]), 1e-12f);
}

__global__ void pnorm_kernel(const float* __restrict__ p_w) {
    int b = blockIdx.x;
    int o = blockIdx.y * 256 + threadIdx.x;
    const float* base = p_w + (size_t)b * Cq * Cq + o;
    float s = 0.f;
    #pragma unroll 4
    for (int c = 0; c < Cq; ++c) {
        float v = base[(size_t)c * Cq];
        s = fmaf(v, v, s);
    }
    g_inv_pnorm[b * Cq + o] = 1.f / fmaxf(sqrtf(s), 1e-12f);
}

// Transpose p_w[b][c][o]*p_g[b][c] -> packed [b*1024+o rows][c cols] bf16 split
__global__ __launch_bounds__(256) void pw_prep_kernel(
    const float* __restrict__ p_w, const float* __restrict__ p_g) {
    int b = blockIdx.z;
    int c0 = blockIdx.x * 32;
    int o0 = blockIdx.y * 32;
    __shared__ float s[32][33];
    __shared__ float pgs[32];
    int tid = threadIdx.x;
    int x = tid & 31, y = tid >> 5;
    if (tid < 32) pgs[tid] = p_g[b * Cq + c0 + tid];
    const float* in = p_w + (size_t)b * Cq * Cq;
    #pragma unroll
    for (int yy = 0; yy < 4; ++yy) {
        int c = c0 + y * 4 + yy;
        s[y * 4 + yy][x] = in[(size_t)c * Cq + o0 + x];
    }
    __syncthreads();
    int q = c0 >> 5;
    int sseg = x >> 3;
    int ins = (x & 7) << 1;
    #pragma unroll
    for (int yy = 0; yy < 4; ++yy) {
        int o = o0 + y * 4 + yy;
        float w = s[x][y * 4 + yy] * pgs[x];
        __nv_bfloat16 h, l;
        bsplit(w, h, l);
        int m = (b << 3) | (o >> 7);
        size_t off = pk_off(m, q, o & 127, sseg, 32) + ins;
        *(__nv_bfloat16*)((char*)g_pwhi + off) = h;
        *(__nv_bfloat16*)((char*)g_pwlo + off) = l;
    }
}

// ===========================================================================
// Depthwise conv v2 on [t][c] layout -> packed bf16 split.
// t-block 16 (halo amp 1.5x vs 2x), c-block 512, smem 24x512 fp32 = 48KB.
// ===========================================================================
__global__ __launch_bounds__(256) void conv_t_kernel(
    const float* __restrict__ d_w, const float* __restrict__ d_g,
    const float* __restrict__ d_b) {
    int b  = blockIdx.z;
    int t0 = blockIdx.y * 16;
    int ch = blockIdx.x * 512;
    __shared__ float s[24][512];
    const float* h = g_hT + (size_t)b * Tq * Cq;
    int tid = threadIdx.x;
    #pragma unroll
    for (int i = 0; i < 12; ++i) {
        int idx = tid + i * 256;
        int r  = idx >> 7;            // 0..23
        int cc = (idx & 127) * 4;
        int t = t0 - 4 + r;
        float4 v = (t >= 0 && t < Tq)
            ? *(const float4*)(h + (size_t)t * Cq + ch + cc)
            : make_float4(0.f, 0.f, 0.f, 0.f);
        *(float4*)&s[r][cc] = v;
    }
    __syncthreads();
    int cg = (tid & 127) * 4;
    int tsub = tid >> 7;              // 0..1 -> t-local 8-row group
    int c = ch + cg;
    float w[Kq][4], bias[4];
    #pragma unroll
    for (int qd = 0; qd < 4; ++qd) {
        float g = d_g[b * Cq + c + qd];
        bias[qd] = d_b[b * Cq + c + qd];
        #pragma unroll
        for (int k = 0; k < Kq; ++k)
            w[k][qd] = d_w[((size_t)b * Cq + c + qd) * Kq + k] * g_inv_dnorm[b * Kq + k] * g;
    }
    int qc = c >> 5;
    int sc = (c >> 3) & 3;
    int ins = (c & 7) << 1;
    #pragma unroll
    for (int i = 0; i < 8; ++i) {
        int tl = tsub * 8 + i;        // 0..15
        int t = t0 + tl;
        float4 acc = make_float4(bias[0], bias[1], bias[2], bias[3]);
        #pragma unroll
        for (int k = 0; k < Kq; ++k) {
            float4 vv = *(float4*)&s[tl + k][cg];
            acc.x = fmaf(vv.x, w[k][0], acc.x);
            acc.y = fmaf(vv.y, w[k][1], acc.y);
            acc.z = fmaf(vv.z, w[k][2], acc.z);
            acc.w = fmaf(vv.w, w[k][3], acc.w);
        }
        __nv_bfloat16 h0, h1, h2, h3, l0, l1, l2, l3;
        bsplit(acc.x, h0, l0); bsplit(acc.y, h1, l1);
        bsplit(acc.z, h2, l2); bsplit(acc.w, h3, l3);
        int m = (b << 3) | (t >> 7);
        size_t off = pk_off(m, qc, t & 127, sc, 32) + ins;
        *(uint2*)((char*)g_convhi + off) = make_uint2(pkbf(h0,h1), pkbf(h2,h3));
        *(uint2*)((char*)g_convlo + off) = make_uint2(pkbf(l0,l1), pkbf(l2,l3));
    }
}

// ===========================================================================
// mma.sync bf16-split GEMM with cp.async.bulk chunk loads.
// CTA tile 128x128, K-chunk 32, 2 stages x 32KB, 2 CTAs/SM.
// Decoupled sync: consumers bar.arrive per chunk; warp 0 bar.syncs + refills.
// ===========================================================================
#define STAGE_B 32768
#define SMEM_ALLOC (1024 + 128 + 2 * STAGE_B)

__device__ __forceinline__ void issue_chunk(uint32_t st0, uint32_t mbf,
    const char* Ah, const char* Al, const char* Bh, const char* Bl, int q) {
    int buf = q & 1;
    uint32_t mb = mbf + (uint32_t)buf * 8u;
    uint32_t dst = st0 + (uint32_t)buf * STAGE_B;
    size_t qo = (size_t)q << 13;
    mbar_expect(mb, 32768u);
    bulk_ld(dst,          Ah + qo, mb);
    bulk_ld(dst + 8192u,  Al + qo, mb);
    bulk_ld(dst + 16384u, Bh + qo, mb);
    bulk_ld(dst + 24576u, Bl + qo, mb);
}

template <int EPI>
__global__ __launch_bounds__(256, 2) void mma_gemm(
    const __nv_bfloat16* __restrict__ Ahi, const __nv_bfloat16* __restrict__ Alo,
    int a_mpb,
    const __nv_bfloat16* __restrict__ Bhi, const __nv_bfloat16* __restrict__ Blo,
    int b_mpb,
    int nchunks,
    const float* __restrict__ e0, const float* __restrict__ e1,
    float* __restrict__ out0) {
    extern __shared__ __align__(128) char dsm[];
    uint32_t raw = smem_to_u32(dsm);
    uint32_t hdr = (raw + 1023u) & ~1023u;
    uint32_t mbf = hdr;
    uint32_t st0 = hdr + 128;
    int tid = threadIdx.x;
    int wid = tid >> 5, lane = tid & 31;
    int wm = wid >> 2, wn = wid & 3;
    int b = blockIdx.z, m0 = blockIdx.y * 128, n0 = blockIdx.x * 128;

    const char* Abh = (const char*)Ahi + ((size_t)((b * a_mpb + blockIdx.y) * nchunks) << 13);
    const char* Abl = (const char*)Alo + ((size_t)((b * a_mpb + blockIdx.y) * nchunks) << 13);
    const char* Bbh = (const char*)Bhi + ((size_t)((b * b_mpb + blockIdx.x) * nchunks) << 13);
    const char* Bbl = (const char*)Blo + ((size_t)((b * b_mpb + blockIdx.x) * nchunks) << 13);

    if (tid == 0) {
        MBARRIER_INIT(mbf, 1);
        MBARRIER_INIT(mbf + 8, 1);
    }
    __syncthreads();
    if (tid == 0) {
        issue_chunk(st0, mbf, Abh, Abl, Bbh, Bbl, 0);
        issue_chunk(st0, mbf, Abh, Abl, Bbh, Bbl, 1);
    }

    uint32_t aoff[4][2], boff4[2][2];
    {
        int rla = lane & 15, sha = (lane >> 4) & 1;
        #pragma unroll
        for (int i = 0; i < 4; ++i) {
            int r = wm * 64 + i * 16 + rla;
            int p = r >> 1, x4 = (r & 1) << 2, mk = p & 7, rb = p << 7;
            aoff[i][0] = rb + (((x4 | sha) ^ mk) << 4);
            aoff[i][1] = rb + (((x4 | (2 + sha)) ^ mk) << 4);
        }
        int rlb = lane & 7;
        int shb = (lane >> 3) & 1;
        int jsel = (lane >> 4) & 1;
        #pragma unroll
        for (int J = 0; J < 2; ++J) {
            int r = wn * 32 + (J * 2 + jsel) * 8 + rlb;
            int p = r >> 1, x4 = (r & 1) << 2, mk = p & 7, rb = p << 7;
            boff4[J][0] = rb + (((x4 | shb) ^ mk) << 4);
            boff4[J][1] = rb + (((x4 | (2 + shb)) ^ mk) << 4);
        }
    }

    float acc[4][4][4] = {};

    for (int q = 0; q < nchunks; ++q) {
        int buf = q & 1;
        MBARRIER_WAIT_PARITY(mbf + (uint32_t)buf * 8u, (q >> 1) & 1);
        uint32_t st = st0 + (uint32_t)buf * STAGE_B;
        #pragma unroll
        for (int ks = 0; ks < 2; ++ks) {
            uint32_t ah[4][4], al[4][4], bh[4][2], bl[4][2];
            #pragma unroll
            for (int J = 0; J < 2; ++J) {
                LDSM_X4(&bh[J * 2][0], st + 16384u + boff4[J][ks]);
                LDSM_X4(&bl[J * 2][0], st + 24576u + boff4[J][ks]);
            }
            #pragma unroll
            for (int i = 0; i < 4; ++i)
                LDSM_X4(ah[i], st + aoff[i][ks]);
            #pragma unroll
            for (int i = 0; i < 4; ++i)
                #pragma unroll
                for (int jj = 0; jj < 4; ++jj)
                    MMA_BF16(acc[i][jj], ah[i], bh[jj]);
            #pragma unroll
            for (int i = 0; i < 4; ++i)
                LDSM_X4(al[i], st + 8192u + aoff[i][ks]);
            #pragma unroll
            for (int i = 0; i < 4; ++i)
                #pragma unroll
                for (int jj = 0; jj < 4; ++jj)
                    MMA_BF16(acc[i][jj], ah[i], bl[jj]);
            #pragma unroll
            for (int i = 0; i < 4; ++i)
                #pragma unroll
                for (int jj = 0; jj < 4; ++jj)
                    MMA_BF16(acc[i][jj], al[i], bh[jj]);
        }
        if (q + 2 < nchunks) {
            int barid = 1 + buf;
            if (wid != 0) {
                BAR_ARRIVE(barid);
            } else {
                BAR_SYNC(barid);
                if (tid == 0)
                    issue_chunk(st0, mbf, Abh, Abl, Bbh, Bbl, q + 2);
            }
        }
    }

    int gid = lane >> 2, tig = lane & 3;
    #pragma unroll
    for (int i = 0; i < 4; ++i) {
        int r0 = m0 + wm * 64 + i * 16 + gid;
        #pragma unroll
        for (int jj = 0; jj < 4; ++jj) {
            int col = n0 + wn * 32 + jj * 8 + tig * 2;
            float v0 = acc[i][jj][0], v1 = acc[i][jj][1];
            float v2 = acc[i][jj][2], v3 = acc[i][jj][3];
            if (EPI == 1) {
                float b0v = e0[col], b1v = e0[col + 1];
                float* d0 = g_hT + ((size_t)b * Tq + r0) * Cq + col;
                float* d1 = g_hT + ((size_t)b * Tq + r0 + 8) * Cq + col;
                *(float2*)d0 = float2{mishf(v0 + b0v), mishf(v1 + b1v)};
                *(float2*)d1 = float2{mishf(v2 + b0v), mishf(v3 + b1v)};
            } else if (EPI == 2) {
                float s0 = g_inv_pnorm[b * Cq + col], s1 = g_inv_pnorm[b * Cq + col + 1];
                float p0 = e0[b * Cq + col], p1 = e0[b * Cq + col + 1];
                float u0 = mishf(fmaf(v0, s0, p0)), u1 = mishf(fmaf(v1, s1, p1));
                float u2 = mishf(fmaf(v2, s0, p0)), u3 = mishf(fmaf(v3, s1, p1));
                __nv_bfloat16 h0, h1, h2, h3, l0, l1, l2, l3;
                bsplit(u0, h0, l0); bsplit(u1, h1, l1);
                bsplit(u2, h2, l2); bsplit(u3, h3, l3);
                int m = (b << 3) | (r0 >> 7);
                int qp = col >> 5, sp = (col >> 3) & 3, ins = (col & 7) << 1;
                size_t oA = pk_off(m, qp, r0 & 127, sp, 32) + ins;
                size_t oB = pk_off(m, qp, (r0 + 8) & 127, sp, 32) + ins;
                *(uint32_t*)((char*)g_tmphi + oA) = pkbf(h0, h1);
                *(uint32_t*)((char*)g_tmphi + oB) = pkbf(h2, h3);
                *(uint32_t*)((char*)g_tmplo + oA) = pkbf(l0, l1);
                *(uint32_t*)((char*)g_tmplo + oB) = pkbf(l2, l3);
            } else {
                float b0v = e0[col], b1v = e0[col + 1];
                size_t o0i = ((size_t)b * Tq + r0) * Dq + col;
                size_t o1i = ((size_t)b * Tq + r0 + 8) * Dq + col;
                float2 x0 = *(const float2*)(e1 + o0i);
                float2 x1 = *(const float2*)(e1 + o1i);
                *(float2*)(out0 + o0i) = float2{v0 + b0v + x0.x, v1 + b1v + x0.y};
                *(float2*)(out0 + o1i) = float2{v2 + b0v + x1.x, v3 + b1v + x1.y};
            }
        }
    }
}

// ===========================================================================
extern "C" void kernel_launch(void* const* d_in, const int* in_sizes, int n_in,
                              void* d_out, int out_size) {
    const float* x   = (const float*)d_in[0];
    const float* d_w = (const float*)d_in[1];
    const float* d_g = (const float*)d_in[2];
    const float* d_b = (const float*)d_in[3];
    const float* p_w = (const float*)d_in[4];
    const float* p_g = (const float*)d_in[5];
    const float* p_b = (const float*)d_in[6];
    const float* w1  = (const float*)d_in[7];
    const float* b1  = (const float*)d_in[8];
    const float* w2  = (const float*)d_in[9];
    const float* b2  = (const float*)d_in[10];
    float* out = (float*)d_out;

    cudaFuncSetAttribute(mma_gemm<1>, cudaFuncAttributeMaxDynamicSharedMemorySize, SMEM_ALLOC);
    cudaFuncSetAttribute(mma_gemm<2>, cudaFuncAttributeMaxDynamicSharedMemorySize, SMEM_ALLOC);
    cudaFuncSetAttribute(mma_gemm<3>, cudaFuncAttributeMaxDynamicSharedMemorySize, SMEM_ALLOC);

    __nv_bfloat16 *xhi, *xlo, *w1hi, *w1lo, *w2hi, *w2lo;
    __nv_bfloat16 *convhi, *convlo, *pwhi, *pwlo, *tmphi, *tmplo;
    cudaGetSymbolAddress((void**)&xhi, g_xhi);
    cudaGetSymbolAddress((void**)&xlo, g_xlo);
    cudaGetSymbolAddress((void**)&w1hi, g_w1hi);
    cudaGetSymbolAddress((void**)&w1lo, g_w1lo);
    cudaGetSymbolAddress((void**)&w2hi, g_w2hi);
    cudaGetSymbolAddress((void**)&w2lo, g_w2lo);
    cudaGetSymbolAddress((void**)&convhi, g_convhi);
    cudaGetSymbolAddress((void**)&convlo, g_convlo);
    cudaGetSymbolAddress((void**)&pwhi, g_pwhi);
    cudaGetSymbolAddress((void**)&pwlo, g_pwlo);
    cudaGetSymbolAddress((void**)&tmphi, g_tmphi);
    cudaGetSymbolAddress((void**)&tmplo, g_tmplo);

    // Fork a side stream into the capture for independent prep work.
    cudaStream_t s2;
    cudaStreamCreateWithFlags(&s2, cudaStreamNonBlocking);
    cudaEvent_t eFork, eDn, eJoin;
    cudaEventCreateWithFlags(&eFork, cudaEventDisableTiming);
    cudaEventCreateWithFlags(&eDn,   cudaEventDisableTiming);
    cudaEventCreateWithFlags(&eJoin, cudaEventDisableTiming);

    cudaEventRecord(eFork, 0);
    cudaStreamWaitEvent(s2, eFork, 0);

    // Submission order puts gemm1 at index 3 for ncu.
    dnorm_kernel<<<Bq * Kq, 256, 0, s2>>>(d_w);                                   // #0
    cudaEventRecord(eDn, s2);
    split_pack_kernel<<<(Bq * Tq * Dq / 8 + 255) / 256, 256>>>(x, xhi, xlo, 5, 8, Bq * Tq * Dq / 8); // #1
    split_pack_kernel<<<(Cq * Dq / 8 + 255) / 256, 256>>>(w1, w1hi, w1lo, 5, 8, Cq * Dq / 8);        // #2

    // GEMM1 (#3, profiled): h = mish(x @ w1^T + b1)
    mma_gemm<1><<<dim3(Cq / 128, Tq / 128, Bq), 256, SMEM_ALLOC>>>(
        xhi, xlo, Tq / 128, w1hi, w1lo, 0, Dq / 32, b1, nullptr, nullptr);

    // Side stream (concurrent with gemm1 on-device).
    pnorm_kernel<<<dim3(Bq, Cq / 256), 256, 0, s2>>>(p_w);
    pw_prep_kernel<<<dim3(Cq / 32, Cq / 32, Bq), 256, 0, s2>>>(p_w, p_g);
    split_pack_kernel<<<(Dq * Cq / 8 + 255) / 256, 256, 0, s2>>>(w2, w2hi, w2lo, 7, 32, Dq * Cq / 8);
    cudaEventRecord(eJoin, s2);

    cudaStreamWaitEvent(0, eDn, 0);
    conv_t_kernel<<<dim3(Cq / 512, Tq / 16, Bq), 256>>>(d_w, d_g, d_b);

    cudaStreamWaitEvent(0, eJoin, 0);
    // GEMM2: tmp = mish(inv_pnorm*(conv @ pw^T) + p_b)
    mma_gemm<2><<<dim3(Cq / 128, Tq / 128, Bq), 256, SMEM_ALLOC>>>(
        convhi, convlo, Tq / 128, pwhi, pwlo, Cq / 128, Cq / 32, p_b, nullptr, nullptr);

    // GEMM3: out = tmp @ w2^T + b2 + x
    mma_gemm<3><<<dim3(Dq / 128, Tq / 128, Bq), 256, SMEM_ALLOC>>>(
        tmphi, tmplo, Tq / 128, w2hi, w2lo, 0, Cq / 32, b2, x, out);
}

// round 16
// speedup vs baseline: 1.0855x; 1.0051x over previous
#include <cuda_runtime.h>
#include <cuda_bf16.h>
#include <cstdint>
#include <math.h>

#define Bq  16
#define Tq  1024
#define Dq  256
#define Cq  1024
#define Kq  9

// ===========================================================================
// Helpers (baseline PTX only — no 'a'-suffix features)
// ===========================================================================
__device__ __forceinline__ uint32_t smem_to_u32(const void* p) {
    uint32_t a;
    asm("{ .reg .u64 t; cvta.to.shared.u64 t, %1; cvt.u32.u64 %0, t; }" : "=r"(a) : "l"(p));
    return a;
}
#define LDSM_X4(r, a) \
    asm volatile("ldmatrix.sync.aligned.m8n8.x4.shared.b16 {%0,%1,%2,%3}, [%4];" \
        : "=r"((r)[0]), "=r"((r)[1]), "=r"((r)[2]), "=r"((r)[3]) : "r"(a))
#define MMA_BF16(d, a, bb) \
    asm volatile("mma.sync.aligned.m16n8k16.row.col.f32.bf16.bf16.f32 " \
        "{%0,%1,%2,%3}, {%4,%5,%6,%7}, {%8,%9}, {%0,%1,%2,%3};" \
        : "+f"((d)[0]), "+f"((d)[1]), "+f"((d)[2]), "+f"((d)[3]) \
        : "r"((a)[0]), "r"((a)[1]), "r"((a)[2]), "r"((a)[3]), \
          "r"((bb)[0]), "r"((bb)[1]))

#define MBARRIER_INIT(mb, c) \
    asm volatile("mbarrier.init.shared.b64 [%0], %1;" :: "r"((uint32_t)(mb)), "r"((uint32_t)(c)) : "memory")
#define MBARRIER_WAIT_PARITY(mb, ph) do { \
    uint32_t _m = (uint32_t)(mb); uint32_t _p = (uint32_t)(ph); uint32_t _d; \
    asm volatile("{\n\t.reg .pred p;\n\t" \
        "mbarrier.try_wait.parity.acquire.cta.shared::cta.b64 p, [%1], %2;\n\t" \
        "selp.b32 %0, 1, 0, p;\n\t}" : "=r"(_d) : "r"(_m), "r"(_p) : "memory"); \
    if (!_d) { \
        asm volatile("{\n\t.reg .pred P1;\n\t" \
            "WL_%=:\n\t" \
            "mbarrier.try_wait.parity.acquire.cta.shared::cta.b64 P1, [%0], %1, 0x989680;\n\t" \
            "@P1 bra.uni WD_%=;\n\t" \
            "bra.uni WL_%=;\n\t" \
            "WD_%=:\n\t}" :: "r"(_m), "r"(_p) : "memory"); \
    } } while (0)

// Named-barrier producer/consumer: warps 1..7 arrive (non-blocking),
// warp 0 syncs (blocks until all 256 arrivals) before refilling the buffer.
#define BAR_ARRIVE(id) asm volatile("bar.arrive %0, 256;" :: "r"(id) : "memory")
#define BAR_SYNC(id)   asm volatile("bar.sync %0, 256;"   :: "r"(id) : "memory")

__device__ __forceinline__ void bulk_ld(uint32_t dst, const void* src, uint32_t mb) {
    asm volatile(
        "cp.async.bulk.shared::cta.global.mbarrier::complete_tx::bytes [%0], [%1], %2, [%3];"
        :: "r"(dst), "l"(src), "r"(8192u), "r"(mb) : "memory");
}
__device__ __forceinline__ void mbar_expect(uint32_t mb, uint32_t bytes) {
    asm volatile("mbarrier.arrive.expect_tx.shared.b64 _, [%0], %1;"
        :: "r"(mb), "r"(bytes) : "memory");
}

// mish(x) = x * w / (w + 2),  w = e^x (e^x + 2). Branch-free: clamp exp at 15.
__device__ __forceinline__ float mishf(float x) {
    float t = __expf(fminf(x, 15.f));
    float w = t * (t + 2.f);
    return x * __fdividef(w, w + 2.f);
}
__device__ __forceinline__ void bsplit(float v, __nv_bfloat16& h, __nv_bfloat16& l) {
    h = __float2bfloat16(v);
    l = __float2bfloat16(v - __bfloat162float(h));
}
__device__ __forceinline__ uint32_t pkbf(__nv_bfloat16 a, __nv_bfloat16 b) {
    __nv_bfloat162 t{a, b};
    return *(uint32_t*)&t;
}

// Packed layout: matrix [R rows][K cols] bf16 -> blocks of 128 rows x 32 k
// (8192 B, chunk-contiguous). Within block: phys row p = r>>1 (128 B),
// 16B segment index = (((r&1)<<2)|s) ^ (p&7), s = (k%32)>>3.
__device__ __forceinline__ size_t pk_off(int m, int q, int r, int s, int nq) {
    int p = r >> 1;
    int seg = ((((r & 1) << 2) | s) ^ (p & 7));
    return ((size_t)(m * nq + q) << 13) + ((size_t)p << 7) + ((size_t)seg << 4);
}

// ===========================================================================
// Device scratch
// ===========================================================================
__device__ __align__(16) __nv_bfloat16 g_xhi[(size_t)Bq * Tq * Dq];     // packed
__device__ __align__(16) __nv_bfloat16 g_xlo[(size_t)Bq * Tq * Dq];
__device__ __align__(16) __nv_bfloat16 g_w1hi[(size_t)Cq * Dq];         // packed
__device__ __align__(16) __nv_bfloat16 g_w1lo[(size_t)Cq * Dq];
__device__ __align__(16) __nv_bfloat16 g_w2hi[(size_t)Dq * Cq];         // packed
__device__ __align__(16) __nv_bfloat16 g_w2lo[(size_t)Dq * Cq];
__device__ __align__(16) float g_hT[(size_t)Bq * Tq * Cq];              // plain [b][t][c]
__device__ __align__(16) __nv_bfloat16 g_convhi[(size_t)Bq * Tq * Cq];  // packed
__device__ __align__(16) __nv_bfloat16 g_convlo[(size_t)Bq * Tq * Cq];
__device__ __align__(16) __nv_bfloat16 g_pwhi[(size_t)Bq * Cq * Cq];    // packed
__device__ __align__(16) __nv_bfloat16 g_pwlo[(size_t)Bq * Cq * Cq];
__device__ __align__(16) __nv_bfloat16 g_tmphi[(size_t)Bq * Tq * Cq];   // packed
__device__ __align__(16) __nv_bfloat16 g_tmplo[(size_t)Bq * Tq * Cq];
__device__ float g_inv_pnorm[Bq * Cq];
__device__ float g_inv_dnorm[Bq * Kq];

// ===========================================================================
// Prep kernels
// ===========================================================================
__global__ void split_pack_kernel(const float* __restrict__ src,
                                  __nv_bfloat16* __restrict__ hi,
                                  __nv_bfloat16* __restrict__ lo,
                                  int lgspr, int nq, int total) {
    int idx = blockIdx.x * 256 + threadIdx.x;
    if (idx >= total) return;
    int spr = 1 << lgspr;
    int r_all = idx >> lgspr;
    int kseg = idx & (spr - 1);
    int q = kseg >> 2, s = kseg & 3;
    int m = r_all >> 7, r = r_all & 127;
    const float* sp = src + ((size_t)r_all << (lgspr + 3)) + ((size_t)kseg << 3);
    float4 v0 = *(const float4*)sp;
    float4 v1 = *(const float4*)(sp + 4);
    __nv_bfloat16 h[8], l[8];
    bsplit(v0.x, h[0], l[0]); bsplit(v0.y, h[1], l[1]);
    bsplit(v0.z, h[2], l[2]); bsplit(v0.w, h[3], l[3]);
    bsplit(v1.x, h[4], l[4]); bsplit(v1.y, h[5], l[5]);
    bsplit(v1.z, h[6], l[6]); bsplit(v1.w, h[7], l[7]);
    size_t off = pk_off(m, q, r, s, nq);
    uint4 hv = make_uint4(pkbf(h[0],h[1]), pkbf(h[2],h[3]), pkbf(h[4],h[5]), pkbf(h[6],h[7]));
    uint4 lv = make_uint4(pkbf(l[0],l[1]), pkbf(l[2],l[3]), pkbf(l[4],l[5]), pkbf(l[6],l[7]));
    *(uint4*)((char*)hi + off) = hv;
    *(uint4*)((char*)lo + off) = lv;
}

__global__ void dnorm_kernel(const float* __restrict__ d_w) {
    int bk = blockIdx.x;
    int b = bk / Kq, k = bk % Kq;
    float s = 0.f;
    for (int c = threadIdx.x; c < Cq; c += 256) {
        float v = d_w[((size_t)b * Cq + c) * Kq + k];
        s = fmaf(v, v, s);
    }
    __shared__ float red[256];
    red[threadIdx.x] = s;
    __syncthreads();
    for (int off = 128; off > 0; off >>= 1) {
        if (threadIdx.x < off) red[threadIdx.x] += red[threadIdx.x + off];
        __syncthreads();
    }
    if (threadIdx.x == 0)
        g_inv_dnorm[bk] = 1.f / fmaxf(sqrtf(red[0]), 1e-12f);
}

__global__ void pnorm_kernel(const float* __restrict__ p_w) {
    int b = blockIdx.x;
    int o = blockIdx.y * 256 + threadIdx.x;
    const float* base = p_w + (size_t)b * Cq * Cq + o;
    float s = 0.f;
    #pragma unroll 4
    for (int c = 0; c < Cq; ++c) {
        float v = base[(size_t)c * Cq];
        s = fmaf(v, v, s);
    }
    g_inv_pnorm[b * Cq + o] = 1.f / fmaxf(sqrtf(s), 1e-12f);
}

// Transpose p_w[b][c][o]*p_g[b][c] -> packed [b*1024+o rows][c cols] bf16 split
__global__ __launch_bounds__(256) void pw_prep_kernel(
    const float* __restrict__ p_w, const float* __restrict__ p_g) {
    int b = blockIdx.z;
    int c0 = blockIdx.x * 32;
    int o0 = blockIdx.y * 32;
    __shared__ float s[32][33];
    __shared__ float pgs[32];
    int tid = threadIdx.x;
    int x = tid & 31, y = tid >> 5;
    if (tid < 32) pgs[tid] = p_g[b * Cq + c0 + tid];
    const float* in = p_w + (size_t)b * Cq * Cq;
    #pragma unroll
    for (int yy = 0; yy < 4; ++yy) {
        int c = c0 + y * 4 + yy;
        s[y * 4 + yy][x] = in[(size_t)c * Cq + o0 + x];
    }
    __syncthreads();
    int q = c0 >> 5;
    int sseg = x >> 3;
    int ins = (x & 7) << 1;
    #pragma unroll
    for (int yy = 0; yy < 4; ++yy) {
        int o = o0 + y * 4 + yy;
        float w = s[x][y * 4 + yy] * pgs[x];
        __nv_bfloat16 h, l;
        bsplit(w, h, l);
        int m = (b << 3) | (o >> 7);
        size_t off = pk_off(m, q, o & 127, sseg, 32) + ins;
        *(__nv_bfloat16*)((char*)g_pwhi + off) = h;
        *(__nv_bfloat16*)((char*)g_pwlo + off) = l;
    }
}

// ===========================================================================
// Depthwise conv v3 on [t][c] layout -> packed bf16 split.
// t-block 32 (halo amp 1.25x), c-block 256, smem 40x256 fp32 = 40KB.
// ===========================================================================
__global__ __launch_bounds__(256) void conv_t_kernel(
    const float* __restrict__ d_w, const float* __restrict__ d_g,
    const float* __restrict__ d_b) {
    int b  = blockIdx.z;
    int t0 = blockIdx.y * 32;
    int ch = blockIdx.x * 256;
    __shared__ float s[40][256];
    const float* h = g_hT + (size_t)b * Tq * Cq;
    int tid = threadIdx.x;
    #pragma unroll
    for (int i = 0; i < 10; ++i) {
        int idx = tid + i * 256;      // 0..2559
        int r  = idx >> 6;            // 0..39 (64 float4 per row)
        int cc = (idx & 63) * 4;
        int t = t0 - 4 + r;
        float4 v = (t >= 0 && t < Tq)
            ? *(const float4*)(h + (size_t)t * Cq + ch + cc)
            : make_float4(0.f, 0.f, 0.f, 0.f);
        *(float4*)&s[r][cc] = v;
    }
    __syncthreads();
    int cg = (tid & 63) * 4;
    int tsub = tid >> 6;              // 0..3 -> t-local 8-row group
    int c = ch + cg;
    float w[Kq][4], bias[4];
    #pragma unroll
    for (int qd = 0; qd < 4; ++qd) {
        float g = d_g[b * Cq + c + qd];
        bias[qd] = d_b[b * Cq + c + qd];
        #pragma unroll
        for (int k = 0; k < Kq; ++k)
            w[k][qd] = d_w[((size_t)b * Cq + c + qd) * Kq + k] * g_inv_dnorm[b * Kq + k] * g;
    }
    int qc = c >> 5;
    int sc = (c >> 3) & 3;
    int ins = (c & 7) << 1;
    #pragma unroll
    for (int i = 0; i < 8; ++i) {
        int tl = tsub * 8 + i;        // 0..31
        int t = t0 + tl;
        float4 acc = make_float4(bias[0], bias[1], bias[2], bias[3]);
        #pragma unroll
        for (int k = 0; k < Kq; ++k) {
            float4 vv = *(float4*)&s[tl + k][cg];
            acc.x = fmaf(vv.x, w[k][0], acc.x);
            acc.y = fmaf(vv.y, w[k][1], acc.y);
            acc.z = fmaf(vv.z, w[k][2], acc.z);
            acc.w = fmaf(vv.w, w[k][3], acc.w);
        }
        __nv_bfloat16 h0, h1, h2, h3, l0, l1, l2, l3;
        bsplit(acc.x, h0, l0); bsplit(acc.y, h1, l1);
        bsplit(acc.z, h2, l2); bsplit(acc.w, h3, l3);
        int m = (b << 3) | (t >> 7);
        size_t off = pk_off(m, qc, t & 127, sc, 32) + ins;
        *(uint2*)((char*)g_convhi + off) = make_uint2(pkbf(h0,h1), pkbf(h2,h3));
        *(uint2*)((char*)g_convlo + off) = make_uint2(pkbf(l0,l1), pkbf(l2,l3));
    }
}

// ===========================================================================
// mma.sync bf16-split GEMM with cp.async.bulk chunk loads.
// CTA tile 128x128, K-chunk 32, 2 stages x 32KB, 2 CTAs/SM.
// Decoupled sync: consumers bar.arrive per chunk; warp 0 bar.syncs + refills.
// ===========================================================================
#define STAGE_B 32768
#define SMEM_ALLOC (1024 + 128 + 2 * STAGE_B)

__device__ __forceinline__ void issue_chunk(uint32_t st0, uint32_t mbf,
    const char* Ah, const char* Al, const char* Bh, const char* Bl, int q) {
    int buf = q & 1;
    uint32_t mb = mbf + (uint32_t)buf * 8u;
    uint32_t dst = st0 + (uint32_t)buf * STAGE_B;
    size_t qo = (size_t)q << 13;
    mbar_expect(mb, 32768u);
    bulk_ld(dst,          Ah + qo, mb);
    bulk_ld(dst + 8192u,  Al + qo, mb);
    bulk_ld(dst + 16384u, Bh + qo, mb);
    bulk_ld(dst + 24576u, Bl + qo, mb);
}

template <int EPI>
__global__ __launch_bounds__(256, 2) void mma_gemm(
    const __nv_bfloat16* __restrict__ Ahi, const __nv_bfloat16* __restrict__ Alo,
    int a_mpb,
    const __nv_bfloat16* __restrict__ Bhi, const __nv_bfloat16* __restrict__ Blo,
    int b_mpb,
    int nchunks,
    const float* __restrict__ e0, const float* __restrict__ e1,
    float* __restrict__ out0) {
    extern __shared__ __align__(128) char dsm[];
    uint32_t raw = smem_to_u32(dsm);
    uint32_t hdr = (raw + 1023u) & ~1023u;
    uint32_t mbf = hdr;
    uint32_t st0 = hdr + 128;
    int tid = threadIdx.x;
    int wid = tid >> 5, lane = tid & 31;
    int wm = wid >> 2, wn = wid & 3;
    int b = blockIdx.z, m0 = blockIdx.y * 128, n0 = blockIdx.x * 128;

    const char* Abh = (const char*)Ahi + ((size_t)((b * a_mpb + blockIdx.y) * nchunks) << 13);
    const char* Abl = (const char*)Alo + ((size_t)((b * a_mpb + blockIdx.y) * nchunks) << 13);
    const char* Bbh = (const char*)Bhi + ((size_t)((b * b_mpb + blockIdx.x) * nchunks) << 13);
    const char* Bbl = (const char*)Blo + ((size_t)((b * b_mpb + blockIdx.x) * nchunks) << 13);

    if (tid == 0) {
        MBARRIER_INIT(mbf, 1);
        MBARRIER_INIT(mbf + 8, 1);
    }
    __syncthreads();
    if (tid == 0) {
        issue_chunk(st0, mbf, Abh, Abl, Bbh, Bbl, 0);
        issue_chunk(st0, mbf, Abh, Abl, Bbh, Bbl, 1);
    }

    uint32_t aoff[4][2], boff4[2][2];
    {
        int rla = lane & 15, sha = (lane >> 4) & 1;
        #pragma unroll
        for (int i = 0; i < 4; ++i) {
            int r = wm * 64 + i * 16 + rla;
            int p = r >> 1, x4 = (r & 1) << 2, mk = p & 7, rb = p << 7;
            aoff[i][0] = rb + (((x4 | sha) ^ mk) << 4);
            aoff[i][1] = rb + (((x4 | (2 + sha)) ^ mk) << 4);
        }
        int rlb = lane & 7;
        int shb = (lane >> 3) & 1;
        int jsel = (lane >> 4) & 1;
        #pragma unroll
        for (int J = 0; J < 2; ++J) {
            int r = wn * 32 + (J * 2 + jsel) * 8 + rlb;
            int p = r >> 1, x4 = (r & 1) << 2, mk = p & 7, rb = p << 7;
            boff4[J][0] = rb + (((x4 | shb) ^ mk) << 4);
            boff4[J][1] = rb + (((x4 | (2 + shb)) ^ mk) << 4);
        }
    }

    float acc[4][4][4] = {};

    for (int q = 0; q < nchunks; ++q) {
        int buf = q & 1;
        MBARRIER_WAIT_PARITY(mbf + (uint32_t)buf * 8u, (q >> 1) & 1);
        uint32_t st = st0 + (uint32_t)buf * STAGE_B;
        #pragma unroll
        for (int ks = 0; ks < 2; ++ks) {
            uint32_t ah[4][4], al[4][4], bh[4][2], bl[4][2];
            #pragma unroll
            for (int J = 0; J < 2; ++J) {
                LDSM_X4(&bh[J * 2][0], st + 16384u + boff4[J][ks]);
                LDSM_X4(&bl[J * 2][0], st + 24576u + boff4[J][ks]);
            }
            #pragma unroll
            for (int i = 0; i < 4; ++i)
                LDSM_X4(ah[i], st + aoff[i][ks]);
            #pragma unroll
            for (int i = 0; i < 4; ++i)
                #pragma unroll
                for (int jj = 0; jj < 4; ++jj)
                    MMA_BF16(acc[i][jj], ah[i], bh[jj]);
            #pragma unroll
            for (int i = 0; i < 4; ++i)
                LDSM_X4(al[i], st + 8192u + aoff[i][ks]);
            #pragma unroll
            for (int i = 0; i < 4; ++i)
                #pragma unroll
                for (int jj = 0; jj < 4; ++jj)
                    MMA_BF16(acc[i][jj], ah[i], bl[jj]);
            #pragma unroll
            for (int i = 0; i < 4; ++i)
                #pragma unroll
                for (int jj = 0; jj < 4; ++jj)
                    MMA_BF16(acc[i][jj], al[i], bh[jj]);
        }
        if (q + 2 < nchunks) {
            int barid = 1 + buf;
            if (wid != 0) {
                BAR_ARRIVE(barid);
            } else {
                BAR_SYNC(barid);
                if (tid == 0)
                    issue_chunk(st0, mbf, Abh, Abl, Bbh, Bbl, q + 2);
            }
        }
    }

    int gid = lane >> 2, tig = lane & 3;
    #pragma unroll
    for (int i = 0; i < 4; ++i) {
        int r0 = m0 + wm * 64 + i * 16 + gid;
        #pragma unroll
        for (int jj = 0; jj < 4; ++jj) {
            int col = n0 + wn * 32 + jj * 8 + tig * 2;
            float v0 = acc[i][jj][0], v1 = acc[i][jj][1];
            float v2 = acc[i][jj][2], v3 = acc[i][jj][3];
            if (EPI == 1) {
                float b0v = e0[col], b1v = e0[col + 1];
                float* d0 = g_hT + ((size_t)b * Tq + r0) * Cq + col;
                float* d1 = g_hT + ((size_t)b * Tq + r0 + 8) * Cq + col;
                *(float2*)d0 = float2{mishf(v0 + b0v), mishf(v1 + b1v)};
                *(float2*)d1 = float2{mishf(v2 + b0v), mishf(v3 + b1v)};
            } else if (EPI == 2) {
                float s0 = g_inv_pnorm[b * Cq + col], s1 = g_inv_pnorm[b * Cq + col + 1];
                float p0 = e0[b * Cq + col], p1 = e0[b * Cq + col + 1];
                float u0 = mishf(fmaf(v0, s0, p0)), u1 = mishf(fmaf(v1, s1, p1));
                float u2 = mishf(fmaf(v2, s0, p0)), u3 = mishf(fmaf(v3, s1, p1));
                __nv_bfloat16 h0, h1, h2, h3, l0, l1, l2, l3;
                bsplit(u0, h0, l0); bsplit(u1, h1, l1);
                bsplit(u2, h2, l2); bsplit(u3, h3, l3);
                int m = (b << 3) | (r0 >> 7);
                int qp = col >> 5, sp = (col >> 3) & 3, ins = (col & 7) << 1;
                size_t oA = pk_off(m, qp, r0 & 127, sp, 32) + ins;
                size_t oB = pk_off(m, qp, (r0 + 8) & 127, sp, 32) + ins;
                *(uint32_t*)((char*)g_tmphi + oA) = pkbf(h0, h1);
                *(uint32_t*)((char*)g_tmphi + oB) = pkbf(h2, h3);
                *(uint32_t*)((char*)g_tmplo + oA) = pkbf(l0, l1);
                *(uint32_t*)((char*)g_tmplo + oB) = pkbf(l2, l3);
            } else {
                float b0v = e0[col], b1v = e0[col + 1];
                size_t o0i = ((size_t)b * Tq + r0) * Dq + col;
                size_t o1i = ((size_t)b * Tq + r0 + 8) * Dq + col;
                float2 x0 = *(const float2*)(e1 + o0i);
                float2 x1 = *(const float2*)(e1 + o1i);
                *(float2*)(out0 + o0i) = float2{v0 + b0v + x0.x, v1 + b1v + x0.y};
                *(float2*)(out0 + o1i) = float2{v2 + b0v + x1.x, v3 + b1v + x1.y};
            }
        }
    }
}

// ===========================================================================
extern "C" void kernel_launch(void* const* d_in, const int* in_sizes, int n_in,
                              void* d_out, int out_size) {
    const float* x   = (const float*)d_in[0];
    const float* d_w = (const float*)d_in[1];
    const float* d_g = (const float*)d_in[2];
    const float* d_b = (const float*)d_in[3];
    const float* p_w = (const float*)d_in[4];
    const float* p_g = (const float*)d_in[5];
    const float* p_b = (const float*)d_in[6];
    const float* w1  = (const float*)d_in[7];
    const float* b1  = (const float*)d_in[8];
    const float* w2  = (const float*)d_in[9];
    const float* b2  = (const float*)d_in[10];
    float* out = (float*)d_out;

    cudaFuncSetAttribute(mma_gemm<1>, cudaFuncAttributeMaxDynamicSharedMemorySize, SMEM_ALLOC);
    cudaFuncSetAttribute(mma_gemm<2>, cudaFuncAttributeMaxDynamicSharedMemorySize, SMEM_ALLOC);
    cudaFuncSetAttribute(mma_gemm<3>, cudaFuncAttributeMaxDynamicSharedMemorySize, SMEM_ALLOC);

    __nv_bfloat16 *xhi, *xlo, *w1hi, *w1lo, *w2hi, *w2lo;
    __nv_bfloat16 *convhi, *convlo, *pwhi, *pwlo, *tmphi, *tmplo;
    cudaGetSymbolAddress((void**)&xhi, g_xhi);
    cudaGetSymbolAddress((void**)&xlo, g_xlo);
    cudaGetSymbolAddress((void**)&w1hi, g_w1hi);
    cudaGetSymbolAddress((void**)&w1lo, g_w1lo);
    cudaGetSymbolAddress((void**)&w2hi, g_w2hi);
    cudaGetSymbolAddress((void**)&w2lo, g_w2lo);
    cudaGetSymbolAddress((void**)&convhi, g_convhi);
    cudaGetSymbolAddress((void**)&convlo, g_convlo);
    cudaGetSymbolAddress((void**)&pwhi, g_pwhi);
    cudaGetSymbolAddress((void**)&pwlo, g_pwlo);
    cudaGetSymbolAddress((void**)&tmphi, g_tmphi);
    cudaGetSymbolAddress((void**)&tmplo, g_tmplo);

    // Fork a side stream into the capture for independent prep work.
    cudaStream_t s2;
    cudaStreamCreateWithFlags(&s2, cudaStreamNonBlocking);
    cudaEvent_t eFork, eDn, eW1, eJoin;
    cudaEventCreateWithFlags(&eFork, cudaEventDisableTiming);
    cudaEventCreateWithFlags(&eDn,   cudaEventDisableTiming);
    cudaEventCreateWithFlags(&eW1,   cudaEventDisableTiming);
    cudaEventCreateWithFlags(&eJoin, cudaEventDisableTiming);

    cudaEventRecord(eFork, 0);
    cudaStreamWaitEvent(s2, eFork, 0);

    // s2: dnorm + w1 split (both off the main critical path).
    dnorm_kernel<<<Bq * Kq, 256, 0, s2>>>(d_w);                                   // #0
    cudaEventRecord(eDn, s2);
    split_pack_kernel<<<(Cq * Dq / 8 + 255) / 256, 256, 0, s2>>>(w1, w1hi, w1lo, 5, 8, Cq * Dq / 8); // #1
    cudaEventRecord(eW1, s2);

    // main: x split (#2), then GEMM1 (#3, profiled).
    split_pack_kernel<<<(Bq * Tq * Dq / 8 + 255) / 256, 256>>>(x, xhi, xlo, 5, 8, Bq * Tq * Dq / 8);
    cudaStreamWaitEvent(0, eW1, 0);
    mma_gemm<1><<<dim3(Cq / 128, Tq / 128, Bq), 256, SMEM_ALLOC>>>(
        xhi, xlo, Tq / 128, w1hi, w1lo, 0, Dq / 32, b1, nullptr, nullptr);

    // s2: remaining prep (concurrent with gemm1 on-device).
    pnorm_kernel<<<dim3(Bq, Cq / 256), 256, 0, s2>>>(p_w);
    pw_prep_kernel<<<dim3(Cq / 32, Cq / 32, Bq), 256, 0, s2>>>(p_w, p_g);
    split_pack_kernel<<<(Dq * Cq / 8 + 255) / 256, 256, 0, s2>>>(w2, w2hi, w2lo, 7, 32, Dq * Cq / 8);
    cudaEventRecord(eJoin, s2);

    cudaStreamWaitEvent(0, eDn, 0);
    conv_t_kernel<<<dim3(Cq / 256, Tq / 32, Bq), 256>>>(d_w, d_g, d_b);

    cudaStreamWaitEvent(0, eJoin, 0);
    // GEMM2: tmp = mish(inv_pnorm*(conv @ pw^T) + p_b)
    mma_gemm<2><<<dim3(Cq / 128, Tq / 128, Bq), 256, SMEM_ALLOC>>>(
        convhi, convlo, Tq / 128, pwhi, pwlo, Cq / 128, Cq / 32, p_b, nullptr, nullptr);

    // GEMM3: out = tmp @ w2^T + b2 + x
    mma_gemm<3><<<dim3(Dq / 128, Tq / 128, Bq), 256, SMEM_ALLOC>>>(
        tmphi, tmplo, Tq / 128, w2hi, w2lo, 0, Cq / 32, b2, x, out);
}